// round 9
// baseline (speedup 1.0000x reference)
#include <cuda_runtime.h>
#include <cuda_fp16.h>
#include <cstdint>
#include <math.h>

// ---------------- problem constants ----------------
#define Cc   192
#define HW   65536           // 256*256
#define NPIX 131072          // B*H*W
#define DWIN 3072            // 16*C
#define NWIN 8192            // B*(H/4)*(W/4)
#define DH   768             // 4*C

// ---------------- scratch (device globals: allocation-free) ----------------
__device__ __half g_wf [(size_t)DWIN * DWIN];      // 18.9 MB  ([K][N] row-major)
__device__ __half g_Xw [(size_t)NWIN * DWIN];      // 50.3 MB
__device__ __half g_Z  [(size_t)NPIX * Cc];        // 50.3 MB
__device__ float  g_X2 [(size_t)NPIX * Cc];        // 100.7 MB (residual chain: fp32)
__device__ __half g_T  [(size_t)NPIX * Cc];        // 50.3 MB
__device__ __half g_U  [(size_t)NPIX * DH];        // 201.3 MB
__device__ __half g_projH[Cc * Cc];
__device__ __half g_fc1H [Cc * DH];
__device__ __half g_fc2H [DH * Cc];

// ---------------- helpers ----------------
__device__ __forceinline__ float gelu_exact(float x) {
    return 0.5f * x * (1.0f + erff(x * 0.70710678118654752f));
}
__device__ __forceinline__ uint32_t smem_u32(const void* p) {
    uint32_t a;
    asm("{ .reg .u64 t; cvta.to.shared.u64 t, %1; cvt.u32.u64 %0, t; }" : "=r"(a) : "l"(p));
    return a;
}

__device__ __forceinline__ int cd_sign16(int i, int j) {
    int s = 1;
    for (int n = 16; n > 1;) {
        int h = n >> 1;
        if (i < h && j < h) {
        } else if (i < h) {
            int t = j - h; j = i; i = t;
        } else if (j < h) {
            if (j != 0) s = -s;
            i = i - h;
        } else {
            int ip = i - h, jp = j - h;
            if (jp == 0) s = -s;
            i = jp; j = ip;
        }
        n = h;
    }
    return s;
}

// ---------------- kernel: build wf (3072 x 3072, [K][N], fp16) -------------
__global__ void build_wf_kernel(const float* __restrict__ w_sed, __half* __restrict__ wf) {
    int e4 = blockIdx.x * blockDim.x + threadIdx.x;
    if (e4 >= DWIN * (DWIN / 4)) return;
    int row  = e4 / (DWIN / 4);
    int col4 = (e4 % (DWIN / 4)) * 4;
    int i = row / Cc, a = row % Cc;
    int k = col4 / Cc, b = col4 % Cc;
    int j = i ^ k;
    float s = (float)cd_sign16(i, j);
    float4 v = *(const float4*)(w_sed + ((size_t)j * Cc + a) * Cc + b);
    __half2* d = (__half2*)(wf + (size_t)row * DWIN + col4);
    d[0] = __floats2half2_rn(s * v.x, s * v.y);
    d[1] = __floats2half2_rn(s * v.z, s * v.w);
}

// ---------------- kernel: fp32 -> fp16 weight convert ----------------------
__global__ void convert_h_kernel(const float* __restrict__ w, __half* __restrict__ wh, int n) {
    int o = blockIdx.x * blockDim.x + threadIdx.x;
    if (o < n) wh[o] = __float2half_rn(w[o]);
}

// ---------------- kernel: LN1 over channels + window scatter (fp16 out) ----
__global__ void ln1_window_kernel(const float* __restrict__ x,
                                  const float* __restrict__ g,
                                  const float* __restrict__ be,
                                  __half* __restrict__ Xw) {
    int n = blockIdx.x * blockDim.x + threadIdx.x;
    if (n >= NPIX) return;
    int b = n >> 16, hw = n & (HW - 1);
    int h = hw >> 8, w = hw & 255;
    const float* px = x + (size_t)b * Cc * HW + hw;
    float s = 0.f, s2 = 0.f;
#pragma unroll 4
    for (int c = 0; c < Cc; c++) {
        float v = px[(size_t)c * HW];
        s += v; s2 += v * v;
    }
    float m  = s * (1.0f / Cc);
    float rs = rsqrtf(s2 * (1.0f / Cc) - m * m + 1e-5f);
    int r = (b << 12) + ((h >> 2) << 6) + (w >> 2);
    int p = ((h & 3) << 2) + (w & 3);
    __half* dst = Xw + (size_t)r * DWIN + p * Cc;
#pragma unroll 4
    for (int c = 0; c < Cc; c++) {
        float v = px[(size_t)c * HW];
        dst[c] = __float2half_rn((v - m) * rs * g[c] + be[c]);
    }
}

// ---------------- kernel: LN2, one warp per row (fp32 in, fp16 out) --------
__global__ void ln2_kernel(const float* __restrict__ X2,
                           const float* __restrict__ g,
                           const float* __restrict__ be,
                           __half* __restrict__ T) {
    int gt   = blockIdx.x * blockDim.x + threadIdx.x;
    int row  = gt >> 5;
    int lane = gt & 31;
    if (row >= NPIX) return;
    const float* src = X2 + (size_t)row * Cc;
    float vals[6];
    float s = 0.f, s2 = 0.f;
#pragma unroll
    for (int i = 0; i < 6; i++) {
        float v = src[lane + i * 32];
        vals[i] = v; s += v; s2 += v * v;
    }
#pragma unroll
    for (int o = 16; o > 0; o >>= 1) {
        s  += __shfl_xor_sync(0xffffffffu, s,  o);
        s2 += __shfl_xor_sync(0xffffffffu, s2, o);
    }
    float m  = s * (1.0f / Cc);
    float rs = rsqrtf(s2 * (1.0f / Cc) - m * m + 1e-5f);
    __half* dst = T + (size_t)row * Cc;
#pragma unroll
    for (int i = 0; i < 6; i++) {
        int c = lane + i * 32;
        dst[c] = __float2half_rn((vals[i] - m) * rs * g[c] + be[c]);
    }
}

// ---------------- MMA helpers ----------------------------------------------
__device__ __forceinline__ void hmma(float* c, const uint32_t* a, const uint32_t* b) {
    asm volatile(
        "mma.sync.aligned.m16n8k16.row.col.f32.f16.f16.f32 "
        "{%0,%1,%2,%3}, {%4,%5,%6,%7}, {%8,%9}, {%0,%1,%2,%3};"
        : "+f"(c[0]), "+f"(c[1]), "+f"(c[2]), "+f"(c[3])
        : "r"(a[0]), "r"(a[1]), "r"(a[2]), "r"(a[3]), "r"(b[0]), "r"(b[1]));
}
__device__ __forceinline__ void hmma_h(uint32_t* c, const uint32_t* a, const uint32_t* b) {
    asm volatile(
        "mma.sync.aligned.m16n8k16.row.col.f16.f16.f16.f16 "
        "{%0,%1}, {%2,%3,%4,%5}, {%6,%7}, {%0,%1};"
        : "+r"(c[0]), "+r"(c[1])
        : "r"(a[0]), "r"(a[1]), "r"(a[2]), "r"(a[3]), "r"(b[0]), "r"(b[1]));
}

#define STG 32768   // bytes per stage (16K A + 16K B; B rows padded to 256B)

// ============================================================================
// Generic fp32-accum GEMM (R8 config: 3-stage, frag double-buffer, 2 CTAs/SM)
// MODE 1: C(fp32) = D + bias + res_bchw
// MODE 2: C(fp16) = gelu(D + bias)
// MODE 3: out_bchw(fp32) = res_rowmaj(fp32) + D + bias
// ============================================================================
template <int MODE, int NT>
__global__ __launch_bounds__(256, 2)
void hgemm(const __half* __restrict__ A, const __half* __restrict__ Bm,
           void* __restrict__ Cv, int M, int N, int K,
           const float* __restrict__ bias, const float* __restrict__ res) {
    extern __shared__ char smem[];
    uint32_t sb = smem_u32(smem);

    int tid  = threadIdx.x;
    int wid  = tid >> 5, lane = tid & 31;
    int wm   = wid & 3;
    int wn   = wid >> 2;
    int row0 = blockIdx.y * 128;
    int col0 = blockIdx.x * (NT * 16);
    int lg   = lane >> 2;
    int lt   = lane & 3;

    float cacc[2][NT][4];
#pragma unroll
    for (int mt = 0; mt < 2; mt++)
#pragma unroll
        for (int nt = 0; nt < NT; nt++)
#pragma unroll
            for (int q = 0; q < 4; q++) cacc[mt][nt][q] = 0.f;

    int nk = K >> 6;

    auto load_stage = [&](int kt, int buf) {
        uint32_t sA = sb + buf * STG;
        uint32_t sB = sA + 16384;
#pragma unroll
        for (int i = 0; i < 4; i++) {
            int idx = tid + i * 256;
            int m = idx >> 3, c = idx & 7;
            const __half* src = A + (size_t)(row0 + m) * K + (kt << 6) + (c << 3);
            uint32_t dst = sA + m * 128 + ((c ^ (m & 7)) << 4);
            asm volatile("cp.async.cg.shared.global [%0], [%1], 16;"
                         :: "r"(dst), "l"(src) : "memory");
        }
#pragma unroll
        for (int i = 0; i < NT / 2; i++) {
            int idx = tid + i * 256;
            int k = idx / (2 * NT), c = idx % (2 * NT);
            int n = col0 + (c << 3);
            const __half* src = Bm + (size_t)((kt << 6) + k) * N + (n < N ? n : 0);
            uint32_t dst = sB + k * 256 + (((c & 8) | ((c & 7) ^ (k & 7))) << 4);
            int ssz = (n < N) ? 16 : 0;
            asm volatile("cp.async.cg.shared.global [%0], [%1], 16, %2;"
                         :: "r"(dst), "l"(src), "r"(ssz) : "memory");
        }
        asm volatile("cp.async.commit_group;" ::: "memory");
    };

    uint32_t af[2][2][4], bf[2][NT][2];
    auto load_frags = [&](uint32_t sA, uint32_t sB, int ks, int pb) {
#pragma unroll
        for (int mt = 0; mt < 2; mt++) {
            int m = wm * 32 + mt * 16 + (lane & 15);
            int c = ks * 2 + (lane >> 4);
            uint32_t addr = sA + m * 128 + ((c ^ (m & 7)) << 4);
            asm volatile("ldmatrix.sync.aligned.m8n8.x4.shared.b16 {%0,%1,%2,%3}, [%4];"
                         : "=r"(af[pb][mt][0]), "=r"(af[pb][mt][1]),
                           "=r"(af[pb][mt][2]), "=r"(af[pb][mt][3])
                         : "r"(addr));
        }
#pragma unroll
        for (int np = 0; np < NT / 2; np++) {
            int k  = ks * 16 + (lane & 15);
            int cn = wn * NT + np * 2 + (lane >> 4);
            uint32_t addr = sB + k * 256 + (((cn & 8) | ((cn & 7) ^ (k & 7))) << 4);
            asm volatile("ldmatrix.sync.aligned.m8n8.x4.trans.shared.b16 {%0,%1,%2,%3}, [%4];"
                         : "=r"(bf[pb][np * 2][0]), "=r"(bf[pb][np * 2][1]),
                           "=r"(bf[pb][np * 2 + 1][0]), "=r"(bf[pb][np * 2 + 1][1])
                         : "r"(addr));
        }
    };

    load_stage(0, 0);
    if (nk > 1) load_stage(1, 1);

    for (int kt = 0; kt < nk; kt++) {
        int buf = kt % 3;
        if (kt + 1 < nk) {
            asm volatile("cp.async.wait_group 1;" ::: "memory");
        } else {
            asm volatile("cp.async.wait_group 0;" ::: "memory");
        }
        __syncthreads();
        if (kt + 2 < nk) load_stage(kt + 2, (kt + 2) % 3);

        uint32_t sA = sb + buf * STG;
        uint32_t sB = sA + 16384;

        load_frags(sA, sB, 0, 0);
#pragma unroll
        for (int ks = 0; ks < 4; ks++) {
            int cur = ks & 1;
            if (ks < 3) load_frags(sA, sB, ks + 1, cur ^ 1);
#pragma unroll
            for (int mt = 0; mt < 2; mt++)
#pragma unroll
                for (int nt = 0; nt < NT; nt++)
                    hmma(cacc[mt][nt], af[cur][mt], bf[cur][nt]);
        }
    }
    __syncthreads();

#pragma unroll
    for (int mt = 0; mt < 2; mt++) {
#pragma unroll
        for (int nt = 0; nt < NT; nt++) {
            int r = row0 + wm * 32 + mt * 16 + lg;
            int c = col0 + wn * (NT * 8) + nt * 8 + lt * 2;
            if (c >= N) continue;
#pragma unroll
            for (int half = 0; half < 2; half++) {
                int rr = r + half * 8;
                float v0 = cacc[mt][nt][half * 2 + 0];
                float v1 = cacc[mt][nt][half * 2 + 1];
                if (MODE == 1) {
                    int rb = rr >> 16, rhw = rr & (HW - 1);
                    const float* rp = res + (size_t)rb * Cc * HW + rhw;
                    float o0 = v0 + bias[c]     + rp[(size_t)c * HW];
                    float o1 = v1 + bias[c + 1] + rp[(size_t)(c + 1) * HW];
                    *(float2*)((float*)Cv + (size_t)rr * N + c) = make_float2(o0, o1);
                } else if (MODE == 2) {
                    *(__half2*)((__half*)Cv + (size_t)rr * N + c) =
                        __floats2half2_rn(gelu_exact(v0 + bias[c]),
                                          gelu_exact(v1 + bias[c + 1]));
                } else {  // MODE 3
                    int rb = rr >> 16, rhw = rr & (HW - 1);
                    const float* rp = res + (size_t)rr * Cc;
                    float* op = (float*)Cv + (size_t)rb * Cc * HW + rhw;
                    op[(size_t)c * HW]       = rp[c]     + v0 + bias[c];
                    op[(size_t)(c + 1) * HW] = rp[c + 1] + v1 + bias[c + 1];
                }
            }
        }
    }
}

// ============================================================================
// GEMM1 kernel: fp16-accumulator HMMA, promoted to fp32 every K=64 chunk.
// Epilogue: gelu + reverse-window scatter to Z (fp16). NT=8 fixed.
// ============================================================================
__global__ __launch_bounds__(256, 2)
void hgemm_g1(const __half* __restrict__ A, const __half* __restrict__ Bm,
              __half* __restrict__ Zo, int M, int N, int K) {
    extern __shared__ char smem[];
    uint32_t sb = smem_u32(smem);

    int tid  = threadIdx.x;
    int wid  = tid >> 5, lane = tid & 31;
    int wm   = wid & 3;
    int wn   = wid >> 2;
    int row0 = blockIdx.y * 128;
    int col0 = blockIdx.x * 128;
    int lg   = lane >> 2;
    int lt   = lane & 3;

    float cacc[2][8][4];
#pragma unroll
    for (int mt = 0; mt < 2; mt++)
#pragma unroll
        for (int nt = 0; nt < 8; nt++)
#pragma unroll
            for (int q = 0; q < 4; q++) cacc[mt][nt][q] = 0.f;

    int nk = K >> 6;

    auto load_stage = [&](int kt, int buf) {
        uint32_t sA = sb + buf * STG;
        uint32_t sB = sA + 16384;
#pragma unroll
        for (int i = 0; i < 4; i++) {
            int idx = tid + i * 256;
            int m = idx >> 3, c = idx & 7;
            const __half* src = A + (size_t)(row0 + m) * K + (kt << 6) + (c << 3);
            uint32_t dst = sA + m * 128 + ((c ^ (m & 7)) << 4);
            asm volatile("cp.async.cg.shared.global [%0], [%1], 16;"
                         :: "r"(dst), "l"(src) : "memory");
        }
#pragma unroll
        for (int i = 0; i < 4; i++) {
            int idx = tid + i * 256;
            int k = idx >> 4, c = idx & 15;
            const __half* src = Bm + (size_t)((kt << 6) + k) * N + col0 + (c << 3);
            uint32_t dst = sB + k * 256 + (((c & 8) | ((c & 7) ^ (k & 7))) << 4);
            asm volatile("cp.async.cg.shared.global [%0], [%1], 16;"
                         :: "r"(dst), "l"(src) : "memory");
        }
        asm volatile("cp.async.commit_group;" ::: "memory");
    };

    load_stage(0, 0);
    load_stage(1, 1);

    for (int kt = 0; kt < nk; kt++) {
        int buf = kt % 3;
        if (kt + 1 < nk) {
            asm volatile("cp.async.wait_group 1;" ::: "memory");
        } else {
            asm volatile("cp.async.wait_group 0;" ::: "memory");
        }
        __syncthreads();
        if (kt + 2 < nk) load_stage(kt + 2, (kt + 2) % 3);

        uint32_t sA = sb + buf * STG;
        uint32_t sB = sA + 16384;

        // fp16 chunk accumulators, zeroed per k-tile
        uint32_t hacc[2][8][2];
#pragma unroll
        for (int mt = 0; mt < 2; mt++)
#pragma unroll
            for (int nt = 0; nt < 8; nt++) { hacc[mt][nt][0] = 0u; hacc[mt][nt][1] = 0u; }

#pragma unroll
        for (int ks = 0; ks < 4; ks++) {
            uint32_t af[2][4], bf[8][2];
#pragma unroll
            for (int mt = 0; mt < 2; mt++) {
                int m = wm * 32 + mt * 16 + (lane & 15);
                int c = ks * 2 + (lane >> 4);
                uint32_t addr = sA + m * 128 + ((c ^ (m & 7)) << 4);
                asm volatile("ldmatrix.sync.aligned.m8n8.x4.shared.b16 {%0,%1,%2,%3}, [%4];"
                             : "=r"(af[mt][0]), "=r"(af[mt][1]), "=r"(af[mt][2]), "=r"(af[mt][3])
                             : "r"(addr));
            }
#pragma unroll
            for (int np = 0; np < 4; np++) {
                int k  = ks * 16 + (lane & 15);
                int cn = wn * 8 + np * 2 + (lane >> 4);
                uint32_t addr = sB + k * 256 + (((cn & 8) | ((cn & 7) ^ (k & 7))) << 4);
                asm volatile("ldmatrix.sync.aligned.m8n8.x4.trans.shared.b16 {%0,%1,%2,%3}, [%4];"
                             : "=r"(bf[np * 2][0]), "=r"(bf[np * 2][1]),
                               "=r"(bf[np * 2 + 1][0]), "=r"(bf[np * 2 + 1][1])
                             : "r"(addr));
            }
#pragma unroll
            for (int mt = 0; mt < 2; mt++)
#pragma unroll
                for (int nt = 0; nt < 8; nt++)
                    hmma_h(hacc[mt][nt], af[mt], bf[nt]);
        }

        // promote chunk into fp32 accumulators
#pragma unroll
        for (int mt = 0; mt < 2; mt++)
#pragma unroll
            for (int nt = 0; nt < 8; nt++) {
                float2 f0 = __half22float2(*(__half2*)&hacc[mt][nt][0]);
                float2 f1 = __half22float2(*(__half2*)&hacc[mt][nt][1]);
                cacc[mt][nt][0] += f0.x; cacc[mt][nt][1] += f0.y;
                cacc[mt][nt][2] += f1.x; cacc[mt][nt][3] += f1.y;
            }
    }
    __syncthreads();

    // epilogue: gelu + reverse-window scatter to Z
#pragma unroll
    for (int mt = 0; mt < 2; mt++) {
#pragma unroll
        for (int nt = 0; nt < 8; nt++) {
            int r = row0 + wm * 32 + mt * 16 + lg;
            int c = col0 + wn * 64 + nt * 8 + lt * 2;
#pragma unroll
            for (int half = 0; half < 2; half++) {
                int rr = r + half * 8;
                float v0 = cacc[mt][nt][half * 2 + 0];
                float v1 = cacc[mt][nt][half * 2 + 1];
                int p  = c / Cc;
                int cc = c - p * Cc;
                int bb = rr >> 12;
                int hq = (rr >> 6) & 63, wq = rr & 63;
                int h = (hq << 2) + (p >> 2), w = (wq << 2) + (p & 3);
                int n = (bb << 16) + (h << 8) + w;
                *(__half2*)(Zo + (size_t)n * Cc + cc) =
                    __floats2half2_rn(gelu_exact(v0), gelu_exact(v1));
            }
        }
    }
}

// ---------------- launch ----------------
extern "C" void kernel_launch(void* const* d_in, const int* in_sizes, int n_in,
                              void* d_out, int out_size) {
    const float* x       = (const float*)d_in[0];
    const float* norm1_g = (const float*)d_in[1];
    const float* norm1_b = (const float*)d_in[2];
    const float* w_sed   = (const float*)d_in[3];
    const float* proj_w  = (const float*)d_in[4];
    const float* proj_b  = (const float*)d_in[5];
    const float* norm2_g = (const float*)d_in[6];
    const float* norm2_b = (const float*)d_in[7];
    const float* fc1_w   = (const float*)d_in[8];
    const float* fc1_b   = (const float*)d_in[9];
    const float* fc2_w   = (const float*)d_in[10];
    const float* fc2_b   = (const float*)d_in[11];
    float* out = (float*)d_out;

    __half *wf, *Xw, *Z, *T, *U, *projH, *fc1H, *fc2H;
    float *X2;
    cudaGetSymbolAddress((void**)&wf,    g_wf);
    cudaGetSymbolAddress((void**)&Xw,    g_Xw);
    cudaGetSymbolAddress((void**)&Z,     g_Z);
    cudaGetSymbolAddress((void**)&X2,    g_X2);
    cudaGetSymbolAddress((void**)&T,     g_T);
    cudaGetSymbolAddress((void**)&U,     g_U);
    cudaGetSymbolAddress((void**)&projH, g_projH);
    cudaGetSymbolAddress((void**)&fc1H,  g_fc1H);
    cudaGetSymbolAddress((void**)&fc2H,  g_fc2H);

    const int SMEM = 3 * STG;  // 98304
    cudaFuncSetAttribute((hgemm<1, 6>), cudaFuncAttributeMaxDynamicSharedMemorySize, SMEM);
    cudaFuncSetAttribute((hgemm<2, 8>), cudaFuncAttributeMaxDynamicSharedMemorySize, SMEM);
    cudaFuncSetAttribute((hgemm<3, 6>), cudaFuncAttributeMaxDynamicSharedMemorySize, SMEM);
    cudaFuncSetAttribute(hgemm_g1, cudaFuncAttributeMaxDynamicSharedMemorySize, SMEM);

    // 0. structured weight + fp16 conversions
    build_wf_kernel<<<(DWIN * (DWIN / 4) + 255) / 256, 256>>>(w_sed, wf);
    convert_h_kernel<<<(Cc * Cc + 255) / 256, 256>>>(proj_w, projH, Cc * Cc);
    convert_h_kernel<<<(Cc * DH + 255) / 256, 256>>>(fc1_w, fc1H, Cc * DH);
    convert_h_kernel<<<(DH * Cc + 255) / 256, 256>>>(fc2_w, fc2H, DH * Cc);

    // 1. LN1 + window partition (fp16)
    ln1_window_kernel<<<(NPIX + 255) / 256, 256>>>(x, norm1_g, norm1_b, Xw);

    // 2. Sedenion GEMM (fp16-accum chunks) + GELU + reverse-window -> Z
    hgemm_g1<<<dim3(DWIN / 128, NWIN / 128), 256, SMEM>>>(
        Xw, wf, Z, NWIN, DWIN, DWIN);

    // 3. proj + bias + residual(x) -> X2 fp32   (131072 x 192 x 192), 96-wide tiles
    hgemm<1, 6><<<dim3(2, NPIX / 128), 256, SMEM>>>(
        Z, projH, X2, NPIX, Cc, Cc, proj_b, x);

    // 4. LN2 -> T (fp16)
    ln2_kernel<<<(NPIX * 32 + 255) / 256, 256>>>(X2, norm2_g, norm2_b, T);

    // 5. fc1 + bias + GELU -> U fp16   (131072 x 768 x 192)
    hgemm<2, 8><<<dim3(DH / 128, NPIX / 128), 256, SMEM>>>(
        T, fc1H, U, NPIX, DH, Cc, fc1_b, nullptr);

    // 6. fc2 + bias + residual(X2), transposed store -> out fp32, 96-wide tiles
    hgemm<3, 6><<<dim3(2, NPIX / 128), 256, SMEM>>>(
        U, fc2H, out, NPIX, Cc, DH, fc2_b, X2);
}

// round 11
// speedup vs baseline: 1.1067x; 1.1067x over previous
#include <cuda_runtime.h>
#include <cuda_fp16.h>
#include <cstdint>
#include <math.h>

// ---------------- problem constants ----------------
#define Cc   192
#define HW   65536           // 256*256
#define NPIX 131072          // B*H*W
#define DWIN 3072            // 16*C
#define NWIN 8192            // B*(H/4)*(W/4)
#define DH   768             // 4*C

// ---------------- scratch (device globals: allocation-free) ----------------
__device__ __half g_wf [(size_t)DWIN * DWIN];      // 18.9 MB  ([K][N] row-major)
__device__ __half g_Xw [(size_t)NWIN * DWIN];      // 50.3 MB
__device__ __half g_Z  [(size_t)NPIX * Cc];        // 50.3 MB
__device__ float  g_X2 [(size_t)NPIX * Cc];        // 100.7 MB (residual chain: fp32)
__device__ __half g_T  [(size_t)NPIX * Cc];        // 50.3 MB
__device__ __half g_U  [(size_t)NPIX * DH];        // 201.3 MB
__device__ __half g_projH[Cc * Cc];
__device__ __half g_fc1H [Cc * DH];
__device__ __half g_fc2H [DH * Cc];

// ---------------- helpers ----------------
__device__ __forceinline__ float gelu_exact(float x) {
    return 0.5f * x * (1.0f + erff(x * 0.70710678118654752f));
}
__device__ __forceinline__ uint32_t smem_u32(const void* p) {
    uint32_t a;
    asm("{ .reg .u64 t; cvta.to.shared.u64 t, %1; cvt.u32.u64 %0, t; }" : "=r"(a) : "l"(p));
    return a;
}

__device__ __forceinline__ int cd_sign16(int i, int j) {
    int s = 1;
    for (int n = 16; n > 1;) {
        int h = n >> 1;
        if (i < h && j < h) {
        } else if (i < h) {
            int t = j - h; j = i; i = t;
        } else if (j < h) {
            if (j != 0) s = -s;
            i = i - h;
        } else {
            int ip = i - h, jp = j - h;
            if (jp == 0) s = -s;
            i = jp; j = ip;
        }
        n = h;
    }
    return s;
}

// ---------------- kernel: build wf (3072 x 3072, [K][N], fp16) -------------
__global__ void build_wf_kernel(const float* __restrict__ w_sed, __half* __restrict__ wf) {
    int e4 = blockIdx.x * blockDim.x + threadIdx.x;
    if (e4 >= DWIN * (DWIN / 4)) return;
    int row  = e4 / (DWIN / 4);
    int col4 = (e4 % (DWIN / 4)) * 4;
    int i = row / Cc, a = row % Cc;
    int k = col4 / Cc, b = col4 % Cc;
    int j = i ^ k;
    float s = (float)cd_sign16(i, j);
    float4 v = *(const float4*)(w_sed + ((size_t)j * Cc + a) * Cc + b);
    __half2* d = (__half2*)(wf + (size_t)row * DWIN + col4);
    d[0] = __floats2half2_rn(s * v.x, s * v.y);
    d[1] = __floats2half2_rn(s * v.z, s * v.w);
}

// ---------------- kernel: fp32 -> fp16 weight convert ----------------------
__global__ void convert_h_kernel(const float* __restrict__ w, __half* __restrict__ wh, int n) {
    int o = blockIdx.x * blockDim.x + threadIdx.x;
    if (o < n) wh[o] = __float2half_rn(w[o]);
}

// ---------------- kernel: LN1 over channels + window scatter (fp16 out) ----
__global__ void ln1_window_kernel(const float* __restrict__ x,
                                  const float* __restrict__ g,
                                  const float* __restrict__ be,
                                  __half* __restrict__ Xw) {
    int n = blockIdx.x * blockDim.x + threadIdx.x;
    if (n >= NPIX) return;
    int b = n >> 16, hw = n & (HW - 1);
    int h = hw >> 8, w = hw & 255;
    const float* px = x + (size_t)b * Cc * HW + hw;
    float s = 0.f, s2 = 0.f;
#pragma unroll 4
    for (int c = 0; c < Cc; c++) {
        float v = px[(size_t)c * HW];
        s += v; s2 += v * v;
    }
    float m  = s * (1.0f / Cc);
    float rs = rsqrtf(s2 * (1.0f / Cc) - m * m + 1e-5f);
    int r = (b << 12) + ((h >> 2) << 6) + (w >> 2);
    int p = ((h & 3) << 2) + (w & 3);
    __half* dst = Xw + (size_t)r * DWIN + p * Cc;
#pragma unroll 4
    for (int c = 0; c < Cc; c++) {
        float v = px[(size_t)c * HW];
        dst[c] = __float2half_rn((v - m) * rs * g[c] + be[c]);
    }
}

// ---------------- kernel: LN2, one warp per row (fp32 in, fp16 out) --------
__global__ void ln2_kernel(const float* __restrict__ X2,
                           const float* __restrict__ g,
                           const float* __restrict__ be,
                           __half* __restrict__ T) {
    int gt   = blockIdx.x * blockDim.x + threadIdx.x;
    int row  = gt >> 5;
    int lane = gt & 31;
    if (row >= NPIX) return;
    const float* src = X2 + (size_t)row * Cc;
    float vals[6];
    float s = 0.f, s2 = 0.f;
#pragma unroll
    for (int i = 0; i < 6; i++) {
        float v = src[lane + i * 32];
        vals[i] = v; s += v; s2 += v * v;
    }
#pragma unroll
    for (int o = 16; o > 0; o >>= 1) {
        s  += __shfl_xor_sync(0xffffffffu, s,  o);
        s2 += __shfl_xor_sync(0xffffffffu, s2, o);
    }
    float m  = s * (1.0f / Cc);
    float rs = rsqrtf(s2 * (1.0f / Cc) - m * m + 1e-5f);
    __half* dst = T + (size_t)row * Cc;
#pragma unroll
    for (int i = 0; i < 6; i++) {
        int c = lane + i * 32;
        dst[c] = __float2half_rn((vals[i] - m) * rs * g[c] + be[c]);
    }
}

// ---------------- fp16 mma.sync GEMM, 3-stage cp.async, 2 CTAs/SM -----------
// Fragment-level double buffering. CTA tile 128 x (NT*16), KT=64.
// 8 warps (4x2), warp tile 32 x (NT*8).
// MODE 1: C(fp32) = D + bias + res_bchw
// MODE 2: C(fp16) = gelu(D + bias)
// MODE 3: out_bchw(fp32) = res_rowmaj(fp32) + D + bias
// MODE 4: Z(fp16) = gelu(D), reverse-window scatter (fused GEMM1 epilogue)
#define STG 32768   // bytes per stage (16K A + 16K B; B rows padded to 256B)

__device__ __forceinline__ void hmma(float* c, const uint32_t* a, const uint32_t* b) {
    asm volatile(
        "mma.sync.aligned.m16n8k16.row.col.f32.f16.f16.f32 "
        "{%0,%1,%2,%3}, {%4,%5,%6,%7}, {%8,%9}, {%0,%1,%2,%3};"
        : "+f"(c[0]), "+f"(c[1]), "+f"(c[2]), "+f"(c[3])
        : "r"(a[0]), "r"(a[1]), "r"(a[2]), "r"(a[3]), "r"(b[0]), "r"(b[1]));
}

template <int MODE, int NT>
__global__ __launch_bounds__(256, 2)
void hgemm(const __half* __restrict__ A, const __half* __restrict__ Bm,
           void* __restrict__ Cv, int M, int N, int K,
           const float* __restrict__ bias, const float* __restrict__ res) {
    extern __shared__ char smem[];
    uint32_t sb = smem_u32(smem);

    int tid  = threadIdx.x;
    int wid  = tid >> 5, lane = tid & 31;
    int wm   = wid & 3;
    int wn   = wid >> 2;
    int row0 = blockIdx.y * 128;
    int col0 = blockIdx.x * (NT * 16);
    int lg   = lane >> 2;
    int lt   = lane & 3;

    float cacc[2][NT][4];
#pragma unroll
    for (int mt = 0; mt < 2; mt++)
#pragma unroll
        for (int nt = 0; nt < NT; nt++)
#pragma unroll
            for (int q = 0; q < 4; q++) cacc[mt][nt][q] = 0.f;

    int nk = K >> 6;

    auto load_stage = [&](int kt, int buf) {
        uint32_t sA = sb + buf * STG;
        uint32_t sB = sA + 16384;
#pragma unroll
        for (int i = 0; i < 4; i++) {
            int idx = tid + i * 256;
            int m = idx >> 3, c = idx & 7;
            const __half* src = A + (size_t)(row0 + m) * K + (kt << 6) + (c << 3);
            uint32_t dst = sA + m * 128 + ((c ^ (m & 7)) << 4);
            asm volatile("cp.async.cg.shared.global [%0], [%1], 16;"
                         :: "r"(dst), "l"(src) : "memory");
        }
        // B: 64 rows x 2*NT 16B-chunks per row
#pragma unroll
        for (int i = 0; i < NT / 2; i++) {
            int idx = tid + i * 256;
            int k = idx / (2 * NT), c = idx % (2 * NT);
            int n = col0 + (c << 3);
            const __half* src = Bm + (size_t)((kt << 6) + k) * N + (n < N ? n : 0);
            uint32_t dst = sB + k * 256 + (((c & 8) | ((c & 7) ^ (k & 7))) << 4);
            int ssz = (n < N) ? 16 : 0;
            asm volatile("cp.async.cg.shared.global [%0], [%1], 16, %2;"
                         :: "r"(dst), "l"(src), "r"(ssz) : "memory");
        }
        asm volatile("cp.async.commit_group;" ::: "memory");
    };

    uint32_t af[2][2][4], bf[2][NT][2];
    auto load_frags = [&](uint32_t sA, uint32_t sB, int ks, int pb) {
#pragma unroll
        for (int mt = 0; mt < 2; mt++) {
            int m = wm * 32 + mt * 16 + (lane & 15);
            int c = ks * 2 + (lane >> 4);
            uint32_t addr = sA + m * 128 + ((c ^ (m & 7)) << 4);
            asm volatile("ldmatrix.sync.aligned.m8n8.x4.shared.b16 {%0,%1,%2,%3}, [%4];"
                         : "=r"(af[pb][mt][0]), "=r"(af[pb][mt][1]),
                           "=r"(af[pb][mt][2]), "=r"(af[pb][mt][3])
                         : "r"(addr));
        }
#pragma unroll
        for (int np = 0; np < NT / 2; np++) {
            int k  = ks * 16 + (lane & 15);
            int cn = wn * NT + np * 2 + (lane >> 4);
            uint32_t addr = sB + k * 256 + (((cn & 8) | ((cn & 7) ^ (k & 7))) << 4);
            asm volatile("ldmatrix.sync.aligned.m8n8.x4.trans.shared.b16 {%0,%1,%2,%3}, [%4];"
                         : "=r"(bf[pb][np * 2][0]), "=r"(bf[pb][np * 2][1]),
                           "=r"(bf[pb][np * 2 + 1][0]), "=r"(bf[pb][np * 2 + 1][1])
                         : "r"(addr));
        }
    };

    load_stage(0, 0);
    if (nk > 1) load_stage(1, 1);

    for (int kt = 0; kt < nk; kt++) {
        int buf = kt % 3;
        if (kt + 1 < nk) {
            asm volatile("cp.async.wait_group 1;" ::: "memory");
        } else {
            asm volatile("cp.async.wait_group 0;" ::: "memory");
        }
        __syncthreads();
        if (kt + 2 < nk) load_stage(kt + 2, (kt + 2) % 3);

        uint32_t sA = sb + buf * STG;
        uint32_t sB = sA + 16384;

        load_frags(sA, sB, 0, 0);
#pragma unroll
        for (int ks = 0; ks < 4; ks++) {
            int cur = ks & 1;
            if (ks < 3) load_frags(sA, sB, ks + 1, cur ^ 1);
#pragma unroll
            for (int mt = 0; mt < 2; mt++)
#pragma unroll
                for (int nt = 0; nt < NT; nt++)
                    hmma(cacc[mt][nt], af[cur][mt], bf[cur][nt]);
        }
    }
    __syncthreads();

    // ---------------- epilogue ----------------
#pragma unroll
    for (int mt = 0; mt < 2; mt++) {
#pragma unroll
        for (int nt = 0; nt < NT; nt++) {
            int r = row0 + wm * 32 + mt * 16 + lg;
            int c = col0 + wn * (NT * 8) + nt * 8 + lt * 2;
            if (c >= N) continue;
#pragma unroll
            for (int half = 0; half < 2; half++) {
                int rr = r + half * 8;
                float v0 = cacc[mt][nt][half * 2 + 0];
                float v1 = cacc[mt][nt][half * 2 + 1];
                if (MODE == 1) {
                    int rb = rr >> 16, rhw = rr & (HW - 1);
                    const float* rp = res + (size_t)rb * Cc * HW + rhw;
                    float o0 = v0 + bias[c]     + rp[(size_t)c * HW];
                    float o1 = v1 + bias[c + 1] + rp[(size_t)(c + 1) * HW];
                    *(float2*)((float*)Cv + (size_t)rr * N + c) = make_float2(o0, o1);
                } else if (MODE == 2) {
                    *(__half2*)((__half*)Cv + (size_t)rr * N + c) =
                        __floats2half2_rn(gelu_exact(v0 + bias[c]),
                                          gelu_exact(v1 + bias[c + 1]));
                } else if (MODE == 3) {
                    int rb = rr >> 16, rhw = rr & (HW - 1);
                    const float* rp = res + (size_t)rr * Cc;
                    float* op = (float*)Cv + (size_t)rb * Cc * HW + rhw;
                    op[(size_t)c * HW]       = rp[c]     + v0 + bias[c];
                    op[(size_t)(c + 1) * HW] = rp[c + 1] + v1 + bias[c + 1];
                } else {  // MODE 4: gelu + reverse-window scatter to Z (fp16)
                    int p  = c / Cc;
                    int cc = c - p * Cc;
                    int bb = rr >> 12;
                    int hq = (rr >> 6) & 63, wq = rr & 63;
                    int h = (hq << 2) + (p >> 2), w = (wq << 2) + (p & 3);
                    int n = (bb << 16) + (h << 8) + w;
                    *(__half2*)((__half*)Cv + (size_t)n * Cc + cc) =
                        __floats2half2_rn(gelu_exact(v0), gelu_exact(v1));
                }
            }
        }
    }
}

// ---------------- launch ----------------
extern "C" void kernel_launch(void* const* d_in, const int* in_sizes, int n_in,
                              void* d_out, int out_size) {
    const float* x       = (const float*)d_in[0];
    const float* norm1_g = (const float*)d_in[1];
    const float* norm1_b = (const float*)d_in[2];
    const float* w_sed   = (const float*)d_in[3];
    const float* proj_w  = (const float*)d_in[4];
    const float* proj_b  = (const float*)d_in[5];
    const float* norm2_g = (const float*)d_in[6];
    const float* norm2_b = (const float*)d_in[7];
    const float* fc1_w   = (const float*)d_in[8];
    const float* fc1_b   = (const float*)d_in[9];
    const float* fc2_w   = (const float*)d_in[10];
    const float* fc2_b   = (const float*)d_in[11];
    float* out = (float*)d_out;

    __half *wf, *Xw, *Z, *T, *U, *projH, *fc1H, *fc2H;
    float *X2;
    cudaGetSymbolAddress((void**)&wf,    g_wf);
    cudaGetSymbolAddress((void**)&Xw,    g_Xw);
    cudaGetSymbolAddress((void**)&Z,     g_Z);
    cudaGetSymbolAddress((void**)&X2,    g_X2);
    cudaGetSymbolAddress((void**)&T,     g_T);
    cudaGetSymbolAddress((void**)&U,     g_U);
    cudaGetSymbolAddress((void**)&projH, g_projH);
    cudaGetSymbolAddress((void**)&fc1H,  g_fc1H);
    cudaGetSymbolAddress((void**)&fc2H,  g_fc2H);

    const int SMEM = 3 * STG;  // 98304
    cudaFuncSetAttribute((hgemm<1, 6>), cudaFuncAttributeMaxDynamicSharedMemorySize, SMEM);
    cudaFuncSetAttribute((hgemm<2, 8>), cudaFuncAttributeMaxDynamicSharedMemorySize, SMEM);
    cudaFuncSetAttribute((hgemm<3, 6>), cudaFuncAttributeMaxDynamicSharedMemorySize, SMEM);
    cudaFuncSetAttribute((hgemm<4, 6>), cudaFuncAttributeMaxDynamicSharedMemorySize, SMEM);

    // 0. structured weight + fp16 conversions
    build_wf_kernel<<<(DWIN * (DWIN / 4) + 255) / 256, 256>>>(w_sed, wf);
    convert_h_kernel<<<(Cc * Cc + 255) / 256, 256>>>(proj_w, projH, Cc * Cc);
    convert_h_kernel<<<(Cc * DH + 255) / 256, 256>>>(fc1_w, fc1H, Cc * DH);
    convert_h_kernel<<<(DH * Cc + 255) / 256, 256>>>(fc2_w, fc2H, DH * Cc);

    // 1. LN1 + window partition (fp16)
    ln1_window_kernel<<<(NPIX + 255) / 256, 256>>>(x, norm1_g, norm1_b, Xw);

    // 2. Sedenion GEMM + GELU + reverse-window scatter -> Z
    //    96-wide tiles: 2048 tiles = 6.92 waves (98.9% util) vs 5.19->6 at 128-wide
    hgemm<4, 6><<<dim3(DWIN / 96, NWIN / 128), 256, SMEM>>>(
        Xw, wf, Z, NWIN, DWIN, DWIN, nullptr, nullptr);

    // 3. proj + bias + residual(x) -> X2 fp32   (131072 x 192 x 192), 96-wide tiles
    hgemm<1, 6><<<dim3(2, NPIX / 128), 256, SMEM>>>(
        Z, projH, X2, NPIX, Cc, Cc, proj_b, x);

    // 4. LN2 -> T (fp16)
    ln2_kernel<<<(NPIX * 32 + 255) / 256, 256>>>(X2, norm2_g, norm2_b, T);

    // 5. fc1 + bias + GELU -> U fp16   (131072 x 768 x 192)
    hgemm<2, 8><<<dim3(DH / 128, NPIX / 128), 256, SMEM>>>(
        T, fc1H, U, NPIX, DH, Cc, fc1_b, nullptr);

    // 6. fc2 + bias + residual(X2), transposed store -> out fp32, 96-wide tiles
    hgemm<3, 6><<<dim3(2, NPIX / 128), 256, SMEM>>>(
        U, fc2H, out, NPIX, Cc, DH, fc2_b, X2);
}

// round 12
// speedup vs baseline: 1.1598x; 1.0480x over previous
#include <cuda_runtime.h>
#include <cuda_fp16.h>
#include <cstdint>
#include <math.h>

// ---------------- problem constants ----------------
#define Cc   192
#define HW   65536           // 256*256
#define NPIX 131072          // B*H*W
#define DWIN 3072            // 16*C
#define NWIN 8192            // B*(H/4)*(W/4)
#define DH   768             // 4*C

// ---------------- scratch (device globals: allocation-free) ----------------
__device__ __half g_wf [(size_t)DWIN * DWIN];      // 18.9 MB  ([K][N] row-major)
__device__ __half g_Xw [(size_t)NWIN * DWIN];      // 50.3 MB
__device__ __half g_Z  [(size_t)NPIX * Cc];        // 50.3 MB
__device__ float  g_X2 [(size_t)NPIX * Cc];        // 100.7 MB (residual chain: fp32)
__device__ __half g_T  [(size_t)NPIX * Cc];        // 50.3 MB
__device__ __half g_U  [(size_t)NPIX * DH];        // 201.3 MB
__device__ __half g_projH[Cc * Cc];
__device__ __half g_fc1H [Cc * DH];
__device__ __half g_fc2H [DH * Cc];

// ---------------- helpers ----------------
__device__ __forceinline__ float gelu_exact(float x) {
    return 0.5f * x * (1.0f + erff(x * 0.70710678118654752f));
}
__device__ __forceinline__ uint32_t smem_u32(const void* p) {
    uint32_t a;
    asm("{ .reg .u64 t; cvta.to.shared.u64 t, %1; cvt.u32.u64 %0, t; }" : "=r"(a) : "l"(p));
    return a;
}

__device__ __forceinline__ int cd_sign16(int i, int j) {
    int s = 1;
    for (int n = 16; n > 1;) {
        int h = n >> 1;
        if (i < h && j < h) {
        } else if (i < h) {
            int t = j - h; j = i; i = t;
        } else if (j < h) {
            if (j != 0) s = -s;
            i = i - h;
        } else {
            int ip = i - h, jp = j - h;
            if (jp == 0) s = -s;
            i = jp; j = ip;
        }
        n = h;
    }
    return s;
}

// ---------------- merged prep kernel -------------------------------------
// Blocks [0, WF_BLK): build wf (3072x3072 fp16, [K][N]) from w_sed
// Blocks [WF_BLK, ...): fp32->fp16 convert of proj_w, fc1_w, fc2_w (float4)
#define WF_E4    (DWIN * (DWIN / 4))          // 2359296 float4-equivalents
#define WF_BLK   (WF_E4 / 256)                // 9216
#define CV_PROJ4 (Cc * Cc / 4)                //  9216 float4
#define CV_FC14  (Cc * DH / 4)                // 36864
#define CV_FC24  (DH * Cc / 4)                // 36864
#define CV_TOT4  (CV_PROJ4 + CV_FC14 + CV_FC24)
#define CV_BLK   ((CV_TOT4 + 255) / 256)      // 324

__global__ void prep_kernel(const float* __restrict__ w_sed, __half* __restrict__ wf,
                            const float* __restrict__ proj_w, __half* __restrict__ projH,
                            const float* __restrict__ fc1_w,  __half* __restrict__ fc1H,
                            const float* __restrict__ fc2_w,  __half* __restrict__ fc2H) {
    int blk = blockIdx.x;
    if (blk < WF_BLK) {
        int e4 = blk * 256 + threadIdx.x;
        int row  = e4 / (DWIN / 4);
        int col4 = (e4 % (DWIN / 4)) * 4;
        int i = row / Cc, a = row % Cc;
        int k = col4 / Cc, b = col4 % Cc;
        int j = i ^ k;
        float s = (float)cd_sign16(i, j);
        float4 v = *(const float4*)(w_sed + ((size_t)j * Cc + a) * Cc + b);
        __half2* d = (__half2*)(wf + (size_t)row * DWIN + col4);
        d[0] = __floats2half2_rn(s * v.x, s * v.y);
        d[1] = __floats2half2_rn(s * v.z, s * v.w);
    } else {
        int e4 = (blk - WF_BLK) * 256 + threadIdx.x;
        const float* src; __half* dst;
        if (e4 < CV_PROJ4) {
            src = proj_w + e4 * 4; dst = projH + e4 * 4;
        } else if (e4 < CV_PROJ4 + CV_FC14) {
            int o = (e4 - CV_PROJ4) * 4; src = fc1_w + o; dst = fc1H + o;
        } else if (e4 < CV_TOT4) {
            int o = (e4 - CV_PROJ4 - CV_FC14) * 4; src = fc2_w + o; dst = fc2H + o;
        } else return;
        float4 v = *(const float4*)src;
        __half2* d = (__half2*)dst;
        d[0] = __floats2half2_rn(v.x, v.y);
        d[1] = __floats2half2_rn(v.z, v.w);
    }
}

// ---------------- kernel: LN1 over channels + window scatter (fp16 out) ----
// block=128 so the per-block x footprint (98 KB) stays L1-resident for pass 2
__global__ void ln1_window_kernel(const float* __restrict__ x,
                                  const float* __restrict__ g,
                                  const float* __restrict__ be,
                                  __half* __restrict__ Xw) {
    int n = blockIdx.x * blockDim.x + threadIdx.x;
    if (n >= NPIX) return;
    int b = n >> 16, hw = n & (HW - 1);
    int h = hw >> 8, w = hw & 255;
    const float* px = x + (size_t)b * Cc * HW + hw;
    float s = 0.f, s2 = 0.f;
#pragma unroll 4
    for (int c = 0; c < Cc; c++) {
        float v = px[(size_t)c * HW];
        s += v; s2 += v * v;
    }
    float m  = s * (1.0f / Cc);
    float rs = rsqrtf(s2 * (1.0f / Cc) - m * m + 1e-5f);
    int r = (b << 12) + ((h >> 2) << 6) + (w >> 2);
    int p = ((h & 3) << 2) + (w & 3);
    __half* dst = Xw + (size_t)r * DWIN + p * Cc;
#pragma unroll 4
    for (int c = 0; c < Cc; c++) {
        float v = px[(size_t)c * HW];
        dst[c] = __float2half_rn((v - m) * rs * g[c] + be[c]);
    }
}

// ---------------- kernel: LN2, one warp per row (fp32 in, fp16 out) --------
__global__ void ln2_kernel(const float* __restrict__ X2,
                           const float* __restrict__ g,
                           const float* __restrict__ be,
                           __half* __restrict__ T) {
    int gt   = blockIdx.x * blockDim.x + threadIdx.x;
    int row  = gt >> 5;
    int lane = gt & 31;
    if (row >= NPIX) return;
    const float* src = X2 + (size_t)row * Cc;
    float vals[6];
    float s = 0.f, s2 = 0.f;
#pragma unroll
    for (int i = 0; i < 6; i++) {
        float v = src[lane + i * 32];
        vals[i] = v; s += v; s2 += v * v;
    }
#pragma unroll
    for (int o = 16; o > 0; o >>= 1) {
        s  += __shfl_xor_sync(0xffffffffu, s,  o);
        s2 += __shfl_xor_sync(0xffffffffu, s2, o);
    }
    float m  = s * (1.0f / Cc);
    float rs = rsqrtf(s2 * (1.0f / Cc) - m * m + 1e-5f);
    __half* dst = T + (size_t)row * Cc;
#pragma unroll
    for (int i = 0; i < 6; i++) {
        int c = lane + i * 32;
        dst[c] = __float2half_rn((vals[i] - m) * rs * g[c] + be[c]);
    }
}

// ---------------- fp16 mma.sync GEMM, 3-stage cp.async, 2 CTAs/SM -----------
// Fragment-level double buffering. CTA tile 128 x (NT*16), KT=64.
// 8 warps (4x2), warp tile 32 x (NT*8).
// MODE 1: C(fp32) = D + bias + res_bchw
// MODE 2: C(fp16) = gelu(D + bias)
// MODE 3: out_bchw(fp32) = res_rowmaj(fp32) + D + bias
// MODE 4: Z(fp16) = gelu(D), reverse-window scatter (fused GEMM1 epilogue)
#define STG 32768   // bytes per stage (16K A + 16K B; B rows padded to 256B)

__device__ __forceinline__ void hmma(float* c, const uint32_t* a, const uint32_t* b) {
    asm volatile(
        "mma.sync.aligned.m16n8k16.row.col.f32.f16.f16.f32 "
        "{%0,%1,%2,%3}, {%4,%5,%6,%7}, {%8,%9}, {%0,%1,%2,%3};"
        : "+f"(c[0]), "+f"(c[1]), "+f"(c[2]), "+f"(c[3])
        : "r"(a[0]), "r"(a[1]), "r"(a[2]), "r"(a[3]), "r"(b[0]), "r"(b[1]));
}

template <int MODE, int NT>
__global__ __launch_bounds__(256, 2)
void hgemm(const __half* __restrict__ A, const __half* __restrict__ Bm,
           void* __restrict__ Cv, int M, int N, int K,
           const float* __restrict__ bias, const float* __restrict__ res) {
    extern __shared__ char smem[];
    uint32_t sb = smem_u32(smem);

    int tid  = threadIdx.x;
    int wid  = tid >> 5, lane = tid & 31;
    int wm   = wid & 3;
    int wn   = wid >> 2;
    int row0 = blockIdx.y * 128;
    int col0 = blockIdx.x * (NT * 16);
    int lg   = lane >> 2;
    int lt   = lane & 3;

    float cacc[2][NT][4];
#pragma unroll
    for (int mt = 0; mt < 2; mt++)
#pragma unroll
        for (int nt = 0; nt < NT; nt++)
#pragma unroll
            for (int q = 0; q < 4; q++) cacc[mt][nt][q] = 0.f;

    int nk = K >> 6;

    auto load_stage = [&](int kt, int buf) {
        uint32_t sA = sb + buf * STG;
        uint32_t sB = sA + 16384;
#pragma unroll
        for (int i = 0; i < 4; i++) {
            int idx = tid + i * 256;
            int m = idx >> 3, c = idx & 7;
            const __half* src = A + (size_t)(row0 + m) * K + (kt << 6) + (c << 3);
            uint32_t dst = sA + m * 128 + ((c ^ (m & 7)) << 4);
            asm volatile("cp.async.cg.shared.global [%0], [%1], 16;"
                         :: "r"(dst), "l"(src) : "memory");
        }
        // B: 64 rows x 2*NT 16B-chunks per row
#pragma unroll
        for (int i = 0; i < NT / 2; i++) {
            int idx = tid + i * 256;
            int k = idx / (2 * NT), c = idx % (2 * NT);
            int n = col0 + (c << 3);
            const __half* src = Bm + (size_t)((kt << 6) + k) * N + (n < N ? n : 0);
            uint32_t dst = sB + k * 256 + (((c & 8) | ((c & 7) ^ (k & 7))) << 4);
            int ssz = (n < N) ? 16 : 0;
            asm volatile("cp.async.cg.shared.global [%0], [%1], 16, %2;"
                         :: "r"(dst), "l"(src), "r"(ssz) : "memory");
        }
        asm volatile("cp.async.commit_group;" ::: "memory");
    };

    uint32_t af[2][2][4], bf[2][NT][2];
    auto load_frags = [&](uint32_t sA, uint32_t sB, int ks, int pb) {
#pragma unroll
        for (int mt = 0; mt < 2; mt++) {
            int m = wm * 32 + mt * 16 + (lane & 15);
            int c = ks * 2 + (lane >> 4);
            uint32_t addr = sA + m * 128 + ((c ^ (m & 7)) << 4);
            asm volatile("ldmatrix.sync.aligned.m8n8.x4.shared.b16 {%0,%1,%2,%3}, [%4];"
                         : "=r"(af[pb][mt][0]), "=r"(af[pb][mt][1]),
                           "=r"(af[pb][mt][2]), "=r"(af[pb][mt][3])
                         : "r"(addr));
        }
#pragma unroll
        for (int np = 0; np < NT / 2; np++) {
            int k  = ks * 16 + (lane & 15);
            int cn = wn * NT + np * 2 + (lane >> 4);
            uint32_t addr = sB + k * 256 + (((cn & 8) | ((cn & 7) ^ (k & 7))) << 4);
            asm volatile("ldmatrix.sync.aligned.m8n8.x4.trans.shared.b16 {%0,%1,%2,%3}, [%4];"
                         : "=r"(bf[pb][np * 2][0]), "=r"(bf[pb][np * 2][1]),
                           "=r"(bf[pb][np * 2 + 1][0]), "=r"(bf[pb][np * 2 + 1][1])
                         : "r"(addr));
        }
    };

    load_stage(0, 0);
    if (nk > 1) load_stage(1, 1);

    for (int kt = 0; kt < nk; kt++) {
        int buf = kt % 3;
        if (kt + 1 < nk) {
            asm volatile("cp.async.wait_group 1;" ::: "memory");
        } else {
            asm volatile("cp.async.wait_group 0;" ::: "memory");
        }
        __syncthreads();
        if (kt + 2 < nk) load_stage(kt + 2, (kt + 2) % 3);

        uint32_t sA = sb + buf * STG;
        uint32_t sB = sA + 16384;

        load_frags(sA, sB, 0, 0);
#pragma unroll
        for (int ks = 0; ks < 4; ks++) {
            int cur = ks & 1;
            if (ks < 3) load_frags(sA, sB, ks + 1, cur ^ 1);
#pragma unroll
            for (int mt = 0; mt < 2; mt++)
#pragma unroll
                for (int nt = 0; nt < NT; nt++)
                    hmma(cacc[mt][nt], af[cur][mt], bf[cur][nt]);
        }
    }
    __syncthreads();

    // ---------------- epilogue ----------------
#pragma unroll
    for (int mt = 0; mt < 2; mt++) {
#pragma unroll
        for (int nt = 0; nt < NT; nt++) {
            int r = row0 + wm * 32 + mt * 16 + lg;
            int c = col0 + wn * (NT * 8) + nt * 8 + lt * 2;
            if (c >= N) continue;
#pragma unroll
            for (int half = 0; half < 2; half++) {
                int rr = r + half * 8;
                float v0 = cacc[mt][nt][half * 2 + 0];
                float v1 = cacc[mt][nt][half * 2 + 1];
                if (MODE == 1) {
                    int rb = rr >> 16, rhw = rr & (HW - 1);
                    const float* rp = res + (size_t)rb * Cc * HW + rhw;
                    float o0 = v0 + bias[c]     + rp[(size_t)c * HW];
                    float o1 = v1 + bias[c + 1] + rp[(size_t)(c + 1) * HW];
                    *(float2*)((float*)Cv + (size_t)rr * N + c) = make_float2(o0, o1);
                } else if (MODE == 2) {
                    *(__half2*)((__half*)Cv + (size_t)rr * N + c) =
                        __floats2half2_rn(gelu_exact(v0 + bias[c]),
                                          gelu_exact(v1 + bias[c + 1]));
                } else if (MODE == 3) {
                    int rb = rr >> 16, rhw = rr & (HW - 1);
                    const float* rp = res + (size_t)rr * Cc;
                    float* op = (float*)Cv + (size_t)rb * Cc * HW + rhw;
                    op[(size_t)c * HW]       = rp[c]     + v0 + bias[c];
                    op[(size_t)(c + 1) * HW] = rp[c + 1] + v1 + bias[c + 1];
                } else {  // MODE 4: gelu + reverse-window scatter to Z (fp16)
                    int p  = c / Cc;
                    int cc = c - p * Cc;
                    int bb = rr >> 12;
                    int hq = (rr >> 6) & 63, wq = rr & 63;
                    int h = (hq << 2) + (p >> 2), w = (wq << 2) + (p & 3);
                    int n = (bb << 16) + (h << 8) + w;
                    *(__half2*)((__half*)Cv + (size_t)n * Cc + cc) =
                        __floats2half2_rn(gelu_exact(v0), gelu_exact(v1));
                }
            }
        }
    }
}

// ---------------- launch ----------------
extern "C" void kernel_launch(void* const* d_in, const int* in_sizes, int n_in,
                              void* d_out, int out_size) {
    const float* x       = (const float*)d_in[0];
    const float* norm1_g = (const float*)d_in[1];
    const float* norm1_b = (const float*)d_in[2];
    const float* w_sed   = (const float*)d_in[3];
    const float* proj_w  = (const float*)d_in[4];
    const float* proj_b  = (const float*)d_in[5];
    const float* norm2_g = (const float*)d_in[6];
    const float* norm2_b = (const float*)d_in[7];
    const float* fc1_w   = (const float*)d_in[8];
    const float* fc1_b   = (const float*)d_in[9];
    const float* fc2_w   = (const float*)d_in[10];
    const float* fc2_b   = (const float*)d_in[11];
    float* out = (float*)d_out;

    __half *wf, *Xw, *Z, *T, *U, *projH, *fc1H, *fc2H;
    float *X2;
    cudaGetSymbolAddress((void**)&wf,    g_wf);
    cudaGetSymbolAddress((void**)&Xw,    g_Xw);
    cudaGetSymbolAddress((void**)&Z,     g_Z);
    cudaGetSymbolAddress((void**)&X2,    g_X2);
    cudaGetSymbolAddress((void**)&T,     g_T);
    cudaGetSymbolAddress((void**)&U,     g_U);
    cudaGetSymbolAddress((void**)&projH, g_projH);
    cudaGetSymbolAddress((void**)&fc1H,  g_fc1H);
    cudaGetSymbolAddress((void**)&fc2H,  g_fc2H);

    const int SMEM = 3 * STG;  // 98304
    cudaFuncSetAttribute((hgemm<1, 6>), cudaFuncAttributeMaxDynamicSharedMemorySize, SMEM);
    cudaFuncSetAttribute((hgemm<2, 8>), cudaFuncAttributeMaxDynamicSharedMemorySize, SMEM);
    cudaFuncSetAttribute((hgemm<3, 6>), cudaFuncAttributeMaxDynamicSharedMemorySize, SMEM);
    cudaFuncSetAttribute((hgemm<4, 8>), cudaFuncAttributeMaxDynamicSharedMemorySize, SMEM);

    // 0. merged prep: wf build + all weight fp16 conversions (one launch)
    prep_kernel<<<WF_BLK + CV_BLK, 256>>>(w_sed, wf, proj_w, projH,
                                          fc1_w, fc1H, fc2_w, fc2H);

    // 1. LN1 + window partition (fp16); block=128 keeps pass-2 reads in L1
    ln1_window_kernel<<<NPIX / 128, 128>>>(x, norm1_g, norm1_b, Xw);

    // 2. Sedenion GEMM + GELU + reverse-window scatter -> Z (R8 config, NT=8)
    hgemm<4, 8><<<dim3(DWIN / 128, NWIN / 128), 256, SMEM>>>(
        Xw, wf, Z, NWIN, DWIN, DWIN, nullptr, nullptr);

    // 3. proj + bias + residual(x) -> X2 fp32   (131072 x 192 x 192), 96-wide tiles
    hgemm<1, 6><<<dim3(2, NPIX / 128), 256, SMEM>>>(
        Z, projH, X2, NPIX, Cc, Cc, proj_b, x);

    // 4. LN2 -> T (fp16)
    ln2_kernel<<<(NPIX * 32 + 255) / 256, 256>>>(X2, norm2_g, norm2_b, T);

    // 5. fc1 + bias + GELU -> U fp16   (131072 x 768 x 192)
    hgemm<2, 8><<<dim3(DH / 128, NPIX / 128), 256, SMEM>>>(
        T, fc1H, U, NPIX, DH, Cc, fc1_b, nullptr);

    // 6. fc2 + bias + residual(X2), transposed store -> out fp32, 96-wide tiles
    hgemm<3, 6><<<dim3(2, NPIX / 128), 256, SMEM>>>(
        U, fc2H, out, NPIX, Cc, DH, fc2_b, X2);
}

// round 13
// speedup vs baseline: 1.4023x; 1.2090x over previous
#include <cuda_runtime.h>
#include <cuda_fp16.h>
#include <cstdint>
#include <math.h>

// ---------------- problem constants ----------------
#define Cc   192
#define HW   65536           // 256*256
#define NPIX 131072          // B*H*W
#define DWIN 3072            // 16*C
#define NWIN 8192            // B*(H/4)*(W/4)
#define DH   768             // 4*C

// ---------------- scratch (device globals: allocation-free) ----------------
__device__ __half g_wf [(size_t)DWIN * DWIN];      // 18.9 MB  ([K][N] row-major)
__device__ __half g_Xw [(size_t)NWIN * DWIN];      // 50.3 MB
__device__ __half g_Z  [(size_t)NPIX * Cc];        // 50.3 MB
__device__ float  g_X2 [(size_t)NPIX * Cc];        // 100.7 MB (residual chain: fp32)
__device__ __half g_T  [(size_t)NPIX * Cc];        // 50.3 MB
__device__ __half g_U  [(size_t)NPIX * DH];        // 201.3 MB
__device__ __half g_projH[Cc * Cc];
__device__ __half g_fc1H [Cc * DH];
__device__ __half g_fc2H [DH * Cc];

// ---------------- helpers ----------------
__device__ __forceinline__ float gelu_exact(float x) {
    return 0.5f * x * (1.0f + erff(x * 0.70710678118654752f));
}
__device__ __forceinline__ uint32_t smem_u32(const void* p) {
    uint32_t a;
    asm("{ .reg .u64 t; cvta.to.shared.u64 t, %1; cvt.u32.u64 %0, t; }" : "=r"(a) : "l"(p));
    return a;
}

__device__ __forceinline__ int cd_sign16(int i, int j) {
    int s = 1;
    for (int n = 16; n > 1;) {
        int h = n >> 1;
        if (i < h && j < h) {
        } else if (i < h) {
            int t = j - h; j = i; i = t;
        } else if (j < h) {
            if (j != 0) s = -s;
            i = i - h;
        } else {
            int ip = i - h, jp = j - h;
            if (jp == 0) s = -s;
            i = jp; j = ip;
        }
        n = h;
    }
    return s;
}

// ---------------- merged prep kernel -------------------------------------
#define WF_E4    (DWIN * (DWIN / 4))
#define WF_BLK   (WF_E4 / 256)
#define CV_PROJ4 (Cc * Cc / 4)
#define CV_FC14  (Cc * DH / 4)
#define CV_FC24  (DH * Cc / 4)
#define CV_TOT4  (CV_PROJ4 + CV_FC14 + CV_FC24)
#define CV_BLK   ((CV_TOT4 + 255) / 256)

__global__ void prep_kernel(const float* __restrict__ w_sed, __half* __restrict__ wf,
                            const float* __restrict__ proj_w, __half* __restrict__ projH,
                            const float* __restrict__ fc1_w,  __half* __restrict__ fc1H,
                            const float* __restrict__ fc2_w,  __half* __restrict__ fc2H) {
    int blk = blockIdx.x;
    if (blk < WF_BLK) {
        int e4 = blk * 256 + threadIdx.x;
        int row  = e4 / (DWIN / 4);
        int col4 = (e4 % (DWIN / 4)) * 4;
        int i = row / Cc, a = row % Cc;
        int k = col4 / Cc, b = col4 % Cc;
        int j = i ^ k;
        float s = (float)cd_sign16(i, j);
        float4 v = *(const float4*)(w_sed + ((size_t)j * Cc + a) * Cc + b);
        __half2* d = (__half2*)(wf + (size_t)row * DWIN + col4);
        d[0] = __floats2half2_rn(s * v.x, s * v.y);
        d[1] = __floats2half2_rn(s * v.z, s * v.w);
    } else {
        int e4 = (blk - WF_BLK) * 256 + threadIdx.x;
        const float* src; __half* dst;
        if (e4 < CV_PROJ4) {
            src = proj_w + e4 * 4; dst = projH + e4 * 4;
        } else if (e4 < CV_PROJ4 + CV_FC14) {
            int o = (e4 - CV_PROJ4) * 4; src = fc1_w + o; dst = fc1H + o;
        } else if (e4 < CV_TOT4) {
            int o = (e4 - CV_PROJ4 - CV_FC14) * 4; src = fc2_w + o; dst = fc2H + o;
        } else return;
        float4 v = *(const float4*)src;
        __half2* d = (__half2*)dst;
        d[0] = __floats2half2_rn(v.x, v.y);
        d[1] = __floats2half2_rn(v.z, v.w);
    }
}

// ---------------- kernel: LN1 via smem transpose (coalesced x reads) -------
// Block: 128 threads, 64 consecutive pixels (one (b,h) row segment).
// Phase 1: load 192x64 fp32 tile coalesced into smem (stride 68 pad).
// Phase 2: threads 0..63 each own one pixel; conflict-free smem column read,
//          LN (same accumulation order as before -> identical numerics),
//          uint4 stores of the 384B Xw row.
#define LN1_SMEM (192 * 68 * 4)   // 52224 bytes

__global__ __launch_bounds__(128)
void ln1_window_kernel(const float* __restrict__ x,
                       const float* __restrict__ g,
                       const float* __restrict__ be,
                       __half* __restrict__ Xw) {
    extern __shared__ float s[];   // [192][68]
    int t  = threadIdx.x;
    int n0 = blockIdx.x * 64;
    int b  = n0 >> 16;
    int hw0 = n0 & (HW - 1);
    const float* xb = x + (size_t)b * Cc * HW + hw0;
#pragma unroll
    for (int j = 0; j < 24; j++) {
        int idx = t + j * 128;
        int c = idx >> 4, q = idx & 15;
        float4 v = *(const float4*)(xb + (size_t)c * HW + q * 4);
        float* d = &s[c * 68 + q * 4];
        d[0] = v.x; d[1] = v.y; d[2] = v.z; d[3] = v.w;
    }
    __syncthreads();
    if (t < 64) {
        int n  = n0 + t;
        int hw = n & (HW - 1);
        int h  = hw >> 8, w = hw & 255;
        float sum = 0.f, sum2 = 0.f;
#pragma unroll 4
        for (int c = 0; c < Cc; c++) {
            float v = s[c * 68 + t];
            sum += v; sum2 += v * v;
        }
        float m  = sum * (1.0f / Cc);
        float rs = rsqrtf(sum2 * (1.0f / Cc) - m * m + 1e-5f);
        int r = (b << 12) + ((h >> 2) << 6) + (w >> 2);
        int p = ((h & 3) << 2) + (w & 3);
        __half* dst = Xw + (size_t)r * DWIN + p * Cc;
#pragma unroll
        for (int c8 = 0; c8 < Cc; c8 += 8) {
            __half2 h4[4];
#pragma unroll
            for (int u = 0; u < 4; u++) {
                int c = c8 + u * 2;
                float v0 = (s[(c + 0) * 68 + t] - m) * rs * g[c + 0] + be[c + 0];
                float v1 = (s[(c + 1) * 68 + t] - m) * rs * g[c + 1] + be[c + 1];
                h4[u] = __floats2half2_rn(v0, v1);
            }
            *(uint4*)(dst + c8) = *(uint4*)h4;
        }
    }
}

// ---------------- kernel: LN2, one warp per row (fp32 in, fp16 out) --------
__global__ void ln2_kernel(const float* __restrict__ X2,
                           const float* __restrict__ g,
                           const float* __restrict__ be,
                           __half* __restrict__ T) {
    int gt   = blockIdx.x * blockDim.x + threadIdx.x;
    int row  = gt >> 5;
    int lane = gt & 31;
    if (row >= NPIX) return;
    const float* src = X2 + (size_t)row * Cc;
    float vals[6];
    float s = 0.f, s2 = 0.f;
#pragma unroll
    for (int i = 0; i < 6; i++) {
        float v = src[lane + i * 32];
        vals[i] = v; s += v; s2 += v * v;
    }
#pragma unroll
    for (int o = 16; o > 0; o >>= 1) {
        s  += __shfl_xor_sync(0xffffffffu, s,  o);
        s2 += __shfl_xor_sync(0xffffffffu, s2, o);
    }
    float m  = s * (1.0f / Cc);
    float rs = rsqrtf(s2 * (1.0f / Cc) - m * m + 1e-5f);
    __half* dst = T + (size_t)row * Cc;
#pragma unroll
    for (int i = 0; i < 6; i++) {
        int c = lane + i * 32;
        dst[c] = __float2half_rn((vals[i] - m) * rs * g[c] + be[c]);
    }
}

// ---------------- fp16 mma.sync GEMM, 3-stage cp.async, 2 CTAs/SM -----------
#define STG 32768

__device__ __forceinline__ void hmma(float* c, const uint32_t* a, const uint32_t* b) {
    asm volatile(
        "mma.sync.aligned.m16n8k16.row.col.f32.f16.f16.f32 "
        "{%0,%1,%2,%3}, {%4,%5,%6,%7}, {%8,%9}, {%0,%1,%2,%3};"
        : "+f"(c[0]), "+f"(c[1]), "+f"(c[2]), "+f"(c[3])
        : "r"(a[0]), "r"(a[1]), "r"(a[2]), "r"(a[3]), "r"(b[0]), "r"(b[1]));
}

template <int MODE, int NT>
__global__ __launch_bounds__(256, 2)
void hgemm(const __half* __restrict__ A, const __half* __restrict__ Bm,
           void* __restrict__ Cv, int M, int N, int K,
           const float* __restrict__ bias, const float* __restrict__ res) {
    extern __shared__ char smem[];
    uint32_t sb = smem_u32(smem);

    int tid  = threadIdx.x;
    int wid  = tid >> 5, lane = tid & 31;
    int wm   = wid & 3;
    int wn   = wid >> 2;
    int row0 = blockIdx.y * 128;
    int col0 = blockIdx.x * (NT * 16);
    int lg   = lane >> 2;
    int lt   = lane & 3;

    float cacc[2][NT][4];
#pragma unroll
    for (int mt = 0; mt < 2; mt++)
#pragma unroll
        for (int nt = 0; nt < NT; nt++)
#pragma unroll
            for (int q = 0; q < 4; q++) cacc[mt][nt][q] = 0.f;

    int nk = K >> 6;

    auto load_stage = [&](int kt, int buf) {
        uint32_t sA = sb + buf * STG;
        uint32_t sB = sA + 16384;
#pragma unroll
        for (int i = 0; i < 4; i++) {
            int idx = tid + i * 256;
            int m = idx >> 3, c = idx & 7;
            const __half* src = A + (size_t)(row0 + m) * K + (kt << 6) + (c << 3);
            uint32_t dst = sA + m * 128 + ((c ^ (m & 7)) << 4);
            asm volatile("cp.async.cg.shared.global [%0], [%1], 16;"
                         :: "r"(dst), "l"(src) : "memory");
        }
#pragma unroll
        for (int i = 0; i < NT / 2; i++) {
            int idx = tid + i * 256;
            int k = idx / (2 * NT), c = idx % (2 * NT);
            int n = col0 + (c << 3);
            const __half* src = Bm + (size_t)((kt << 6) + k) * N + (n < N ? n : 0);
            uint32_t dst = sB + k * 256 + (((c & 8) | ((c & 7) ^ (k & 7))) << 4);
            int ssz = (n < N) ? 16 : 0;
            asm volatile("cp.async.cg.shared.global [%0], [%1], 16, %2;"
                         :: "r"(dst), "l"(src), "r"(ssz) : "memory");
        }
        asm volatile("cp.async.commit_group;" ::: "memory");
    };

    uint32_t af[2][2][4], bf[2][NT][2];
    auto load_frags = [&](uint32_t sA, uint32_t sB, int ks, int pb) {
#pragma unroll
        for (int mt = 0; mt < 2; mt++) {
            int m = wm * 32 + mt * 16 + (lane & 15);
            int c = ks * 2 + (lane >> 4);
            uint32_t addr = sA + m * 128 + ((c ^ (m & 7)) << 4);
            asm volatile("ldmatrix.sync.aligned.m8n8.x4.shared.b16 {%0,%1,%2,%3}, [%4];"
                         : "=r"(af[pb][mt][0]), "=r"(af[pb][mt][1]),
                           "=r"(af[pb][mt][2]), "=r"(af[pb][mt][3])
                         : "r"(addr));
        }
#pragma unroll
        for (int np = 0; np < NT / 2; np++) {
            int k  = ks * 16 + (lane & 15);
            int cn = wn * NT + np * 2 + (lane >> 4);
            uint32_t addr = sB + k * 256 + (((cn & 8) | ((cn & 7) ^ (k & 7))) << 4);
            asm volatile("ldmatrix.sync.aligned.m8n8.x4.trans.shared.b16 {%0,%1,%2,%3}, [%4];"
                         : "=r"(bf[pb][np * 2][0]), "=r"(bf[pb][np * 2][1]),
                           "=r"(bf[pb][np * 2 + 1][0]), "=r"(bf[pb][np * 2 + 1][1])
                         : "r"(addr));
        }
    };

    load_stage(0, 0);
    if (nk > 1) load_stage(1, 1);

    for (int kt = 0; kt < nk; kt++) {
        int buf = kt % 3;
        if (kt + 1 < nk) {
            asm volatile("cp.async.wait_group 1;" ::: "memory");
        } else {
            asm volatile("cp.async.wait_group 0;" ::: "memory");
        }
        __syncthreads();
        if (kt + 2 < nk) load_stage(kt + 2, (kt + 2) % 3);

        uint32_t sA = sb + buf * STG;
        uint32_t sB = sA + 16384;

        load_frags(sA, sB, 0, 0);
#pragma unroll
        for (int ks = 0; ks < 4; ks++) {
            int cur = ks & 1;
            if (ks < 3) load_frags(sA, sB, ks + 1, cur ^ 1);
#pragma unroll
            for (int mt = 0; mt < 2; mt++)
#pragma unroll
                for (int nt = 0; nt < NT; nt++)
                    hmma(cacc[mt][nt], af[cur][mt], bf[cur][nt]);
        }
    }
    __syncthreads();

    // ---------------- epilogue ----------------
#pragma unroll
    for (int mt = 0; mt < 2; mt++) {
#pragma unroll
        for (int nt = 0; nt < NT; nt++) {
            int r = row0 + wm * 32 + mt * 16 + lg;
            int c = col0 + wn * (NT * 8) + nt * 8 + lt * 2;
            if (c >= N) continue;
#pragma unroll
            for (int half = 0; half < 2; half++) {
                int rr = r + half * 8;
                float v0 = cacc[mt][nt][half * 2 + 0];
                float v1 = cacc[mt][nt][half * 2 + 1];
                if (MODE == 1) {
                    int rb = rr >> 16, rhw = rr & (HW - 1);
                    const float* rp = res + (size_t)rb * Cc * HW + rhw;
                    float o0 = v0 + bias[c]     + rp[(size_t)c * HW];
                    float o1 = v1 + bias[c + 1] + rp[(size_t)(c + 1) * HW];
                    *(float2*)((float*)Cv + (size_t)rr * N + c) = make_float2(o0, o1);
                } else if (MODE == 2) {
                    *(__half2*)((__half*)Cv + (size_t)rr * N + c) =
                        __floats2half2_rn(gelu_exact(v0 + bias[c]),
                                          gelu_exact(v1 + bias[c + 1]));
                } else if (MODE == 3) {
                    int rb = rr >> 16, rhw = rr & (HW - 1);
                    const float* rp = res + (size_t)rr * Cc;
                    float* op = (float*)Cv + (size_t)rb * Cc * HW + rhw;
                    op[(size_t)c * HW]       = rp[c]     + v0 + bias[c];
                    op[(size_t)(c + 1) * HW] = rp[c + 1] + v1 + bias[c + 1];
                } else {  // MODE 4: gelu + reverse-window scatter to Z (fp16)
                    int p  = c / Cc;
                    int cc = c - p * Cc;
                    int bb = rr >> 12;
                    int hq = (rr >> 6) & 63, wq = rr & 63;
                    int h = (hq << 2) + (p >> 2), w = (wq << 2) + (p & 3);
                    int n = (bb << 16) + (h << 8) + w;
                    *(__half2*)((__half*)Cv + (size_t)n * Cc + cc) =
                        __floats2half2_rn(gelu_exact(v0), gelu_exact(v1));
                }
            }
        }
    }
}

// ---------------- launch ----------------
extern "C" void kernel_launch(void* const* d_in, const int* in_sizes, int n_in,
                              void* d_out, int out_size) {
    const float* x       = (const float*)d_in[0];
    const float* norm1_g = (const float*)d_in[1];
    const float* norm1_b = (const float*)d_in[2];
    const float* w_sed   = (const float*)d_in[3];
    const float* proj_w  = (const float*)d_in[4];
    const float* proj_b  = (const float*)d_in[5];
    const float* norm2_g = (const float*)d_in[6];
    const float* norm2_b = (const float*)d_in[7];
    const float* fc1_w   = (const float*)d_in[8];
    const float* fc1_b   = (const float*)d_in[9];
    const float* fc2_w   = (const float*)d_in[10];
    const float* fc2_b   = (const float*)d_in[11];
    float* out = (float*)d_out;

    __half *wf, *Xw, *Z, *T, *U, *projH, *fc1H, *fc2H;
    float *X2;
    cudaGetSymbolAddress((void**)&wf,    g_wf);
    cudaGetSymbolAddress((void**)&Xw,    g_Xw);
    cudaGetSymbolAddress((void**)&Z,     g_Z);
    cudaGetSymbolAddress((void**)&X2,    g_X2);
    cudaGetSymbolAddress((void**)&T,     g_T);
    cudaGetSymbolAddress((void**)&U,     g_U);
    cudaGetSymbolAddress((void**)&projH, g_projH);
    cudaGetSymbolAddress((void**)&fc1H,  g_fc1H);
    cudaGetSymbolAddress((void**)&fc2H,  g_fc2H);

    const int SMEM = 3 * STG;  // 98304
    cudaFuncSetAttribute((hgemm<1, 6>), cudaFuncAttributeMaxDynamicSharedMemorySize, SMEM);
    cudaFuncSetAttribute((hgemm<2, 8>), cudaFuncAttributeMaxDynamicSharedMemorySize, SMEM);
    cudaFuncSetAttribute((hgemm<3, 6>), cudaFuncAttributeMaxDynamicSharedMemorySize, SMEM);
    cudaFuncSetAttribute((hgemm<4, 8>), cudaFuncAttributeMaxDynamicSharedMemorySize, SMEM);
    cudaFuncSetAttribute(ln1_window_kernel, cudaFuncAttributeMaxDynamicSharedMemorySize, LN1_SMEM);

    // 0. merged prep: wf build + all weight fp16 conversions (one launch)
    prep_kernel<<<WF_BLK + CV_BLK, 256>>>(w_sed, wf, proj_w, projH,
                                          fc1_w, fc1H, fc2_w, fc2H);

    // 1. LN1 + window partition via smem transpose (coalesced x reads)
    ln1_window_kernel<<<NPIX / 64, 128, LN1_SMEM>>>(x, norm1_g, norm1_b, Xw);

    // 2. Sedenion GEMM + GELU + reverse-window scatter -> Z (R8 config, NT=8)
    hgemm<4, 8><<<dim3(DWIN / 128, NWIN / 128), 256, SMEM>>>(
        Xw, wf, Z, NWIN, DWIN, DWIN, nullptr, nullptr);

    // 3. proj + bias + residual(x) -> X2 fp32   (131072 x 192 x 192), 96-wide tiles
    hgemm<1, 6><<<dim3(2, NPIX / 128), 256, SMEM>>>(
        Z, projH, X2, NPIX, Cc, Cc, proj_b, x);

    // 4. LN2 -> T (fp16)
    ln2_kernel<<<(NPIX * 32 + 255) / 256, 256>>>(X2, norm2_g, norm2_b, T);

    // 5. fc1 + bias + GELU -> U fp16   (131072 x 768 x 192)
    hgemm<2, 8><<<dim3(DH / 128, NPIX / 128), 256, SMEM>>>(
        T, fc1H, U, NPIX, DH, Cc, fc1_b, nullptr);

    // 6. fc2 + bias + residual(X2), transposed store -> out fp32, 96-wide tiles
    hgemm<3, 6><<<dim3(2, NPIX / 128), 256, SMEM>>>(
        U, fc2H, out, NPIX, Cc, DH, fc2_b, X2);
}

// round 14
// speedup vs baseline: 1.4251x; 1.0163x over previous
#include <cuda_runtime.h>
#include <cuda_fp16.h>
#include <cstdint>
#include <math.h>

// ---------------- problem constants ----------------
#define Cc   192
#define HW   65536           // 256*256
#define NPIX 131072          // B*H*W
#define DWIN 3072            // 16*C
#define NWIN 8192            // B*(H/4)*(W/4)
#define DH   768             // 4*C

// ---------------- scratch (device globals: allocation-free) ----------------
__device__ __half g_wf [(size_t)DWIN * DWIN];      // 18.9 MB  ([K][N] row-major)
__device__ __half g_Xw [(size_t)NWIN * DWIN];      // 50.3 MB
__device__ __half g_Z  [(size_t)NPIX * Cc];        // 50.3 MB
__device__ __half g_X2 [(size_t)NPIX * Cc];        // 50.3 MB (residual chain: fp16)
__device__ __half g_T  [(size_t)NPIX * Cc];        // 50.3 MB
__device__ __half g_U  [(size_t)NPIX * DH];        // 201.3 MB
__device__ __half g_projH[Cc * Cc];
__device__ __half g_fc1H [Cc * DH];
__device__ __half g_fc2H [DH * Cc];

// ---------------- helpers ----------------
__device__ __forceinline__ float gelu_exact(float x) {
    return 0.5f * x * (1.0f + erff(x * 0.70710678118654752f));
}
__device__ __forceinline__ uint32_t smem_u32(const void* p) {
    uint32_t a;
    asm("{ .reg .u64 t; cvta.to.shared.u64 t, %1; cvt.u32.u64 %0, t; }" : "=r"(a) : "l"(p));
    return a;
}

__device__ __forceinline__ int cd_sign16(int i, int j) {
    int s = 1;
    for (int n = 16; n > 1;) {
        int h = n >> 1;
        if (i < h && j < h) {
        } else if (i < h) {
            int t = j - h; j = i; i = t;
        } else if (j < h) {
            if (j != 0) s = -s;
            i = i - h;
        } else {
            int ip = i - h, jp = j - h;
            if (jp == 0) s = -s;
            i = jp; j = ip;
        }
        n = h;
    }
    return s;
}

// ---------------- merged prep kernel -------------------------------------
#define WF_E4    (DWIN * (DWIN / 4))
#define WF_BLK   (WF_E4 / 256)
#define CV_PROJ4 (Cc * Cc / 4)
#define CV_FC14  (Cc * DH / 4)
#define CV_FC24  (DH * Cc / 4)
#define CV_TOT4  (CV_PROJ4 + CV_FC14 + CV_FC24)
#define CV_BLK   ((CV_TOT4 + 255) / 256)

__global__ void prep_kernel(const float* __restrict__ w_sed, __half* __restrict__ wf,
                            const float* __restrict__ proj_w, __half* __restrict__ projH,
                            const float* __restrict__ fc1_w,  __half* __restrict__ fc1H,
                            const float* __restrict__ fc2_w,  __half* __restrict__ fc2H) {
    int blk = blockIdx.x;
    if (blk < WF_BLK) {
        int e4 = blk * 256 + threadIdx.x;
        int row  = e4 / (DWIN / 4);
        int col4 = (e4 % (DWIN / 4)) * 4;
        int i = row / Cc, a = row % Cc;
        int k = col4 / Cc, b = col4 % Cc;
        int j = i ^ k;
        float s = (float)cd_sign16(i, j);
        float4 v = *(const float4*)(w_sed + ((size_t)j * Cc + a) * Cc + b);
        __half2* d = (__half2*)(wf + (size_t)row * DWIN + col4);
        d[0] = __floats2half2_rn(s * v.x, s * v.y);
        d[1] = __floats2half2_rn(s * v.z, s * v.w);
    } else {
        int e4 = (blk - WF_BLK) * 256 + threadIdx.x;
        const float* src; __half* dst;
        if (e4 < CV_PROJ4) {
            src = proj_w + e4 * 4; dst = projH + e4 * 4;
        } else if (e4 < CV_PROJ4 + CV_FC14) {
            int o = (e4 - CV_PROJ4) * 4; src = fc1_w + o; dst = fc1H + o;
        } else if (e4 < CV_TOT4) {
            int o = (e4 - CV_PROJ4 - CV_FC14) * 4; src = fc2_w + o; dst = fc2H + o;
        } else return;
        float4 v = *(const float4*)src;
        __half2* d = (__half2*)dst;
        d[0] = __floats2half2_rn(v.x, v.y);
        d[1] = __floats2half2_rn(v.z, v.w);
    }
}

// ---------------- kernel: LN1 via smem transpose (coalesced x reads) -------
#define LN1_SMEM (192 * 68 * 4)   // 52224 bytes

__global__ __launch_bounds__(128)
void ln1_window_kernel(const float* __restrict__ x,
                       const float* __restrict__ g,
                       const float* __restrict__ be,
                       __half* __restrict__ Xw) {
    extern __shared__ float s[];   // [192][68]
    int t  = threadIdx.x;
    int n0 = blockIdx.x * 64;
    int b  = n0 >> 16;
    int hw0 = n0 & (HW - 1);
    const float* xb = x + (size_t)b * Cc * HW + hw0;
#pragma unroll
    for (int j = 0; j < 24; j++) {
        int idx = t + j * 128;
        int c = idx >> 4, q = idx & 15;
        float4 v = *(const float4*)(xb + (size_t)c * HW + q * 4);
        float* d = &s[c * 68 + q * 4];
        d[0] = v.x; d[1] = v.y; d[2] = v.z; d[3] = v.w;
    }
    __syncthreads();
    if (t < 64) {
        int n  = n0 + t;
        int hw = n & (HW - 1);
        int h  = hw >> 8, w = hw & 255;
        float sum = 0.f, sum2 = 0.f;
#pragma unroll 4
        for (int c = 0; c < Cc; c++) {
            float v = s[c * 68 + t];
            sum += v; sum2 += v * v;
        }
        float m  = sum * (1.0f / Cc);
        float rs = rsqrtf(sum2 * (1.0f / Cc) - m * m + 1e-5f);
        int r = (b << 12) + ((h >> 2) << 6) + (w >> 2);
        int p = ((h & 3) << 2) + (w & 3);
        __half* dst = Xw + (size_t)r * DWIN + p * Cc;
#pragma unroll
        for (int c8 = 0; c8 < Cc; c8 += 8) {
            __half2 h4[4];
#pragma unroll
            for (int u = 0; u < 4; u++) {
                int c = c8 + u * 2;
                float v0 = (s[(c + 0) * 68 + t] - m) * rs * g[c + 0] + be[c + 0];
                float v1 = (s[(c + 1) * 68 + t] - m) * rs * g[c + 1] + be[c + 1];
                h4[u] = __floats2half2_rn(v0, v1);
            }
            *(uint4*)(dst + c8) = *(uint4*)h4;
        }
    }
}

// ---------------- kernel: LN2, one warp per row (fp16 in, fp16 out) --------
__global__ void ln2_kernel(const __half* __restrict__ X2,
                           const float* __restrict__ g,
                           const float* __restrict__ be,
                           __half* __restrict__ T) {
    int gt   = blockIdx.x * blockDim.x + threadIdx.x;
    int row  = gt >> 5;
    int lane = gt & 31;
    if (row >= NPIX) return;
    const __half* src = X2 + (size_t)row * Cc;
    float vals[6];
    float s = 0.f, s2 = 0.f;
#pragma unroll
    for (int i = 0; i < 3; i++) {
        __half2 hv = *(const __half2*)(src + lane * 2 + i * 64);
        float2 f = __half22float2(hv);
        vals[i * 2] = f.x; vals[i * 2 + 1] = f.y;
        s += f.x + f.y; s2 += f.x * f.x + f.y * f.y;
    }
#pragma unroll
    for (int o = 16; o > 0; o >>= 1) {
        s  += __shfl_xor_sync(0xffffffffu, s,  o);
        s2 += __shfl_xor_sync(0xffffffffu, s2, o);
    }
    float m  = s * (1.0f / Cc);
    float rs = rsqrtf(s2 * (1.0f / Cc) - m * m + 1e-5f);
    __half* dst = T + (size_t)row * Cc;
#pragma unroll
    for (int i = 0; i < 3; i++) {
        int c = lane * 2 + i * 64;
        float v0 = (vals[i * 2]     - m) * rs * g[c]     + be[c];
        float v1 = (vals[i * 2 + 1] - m) * rs * g[c + 1] + be[c + 1];
        *(__half2*)(dst + c) = __floats2half2_rn(v0, v1);
    }
}

// ---------------- fp16 mma.sync GEMM, 3-stage cp.async, 2 CTAs/SM -----------
// MODE 1: X2(fp16) = D + bias + res_bchw(fp32)        (proj + residual)
// MODE 2: C(fp16)  = gelu(D + bias)                   (fc1)
// MODE 3: out_bchw(fp32) = res_rowmaj(fp16) + D + b   (fc2, transposed store)
// MODE 4: Z(fp16)  = gelu(D), reverse-window scatter  (GEMM1 fused)
#define STG 32768

__device__ __forceinline__ void hmma(float* c, const uint32_t* a, const uint32_t* b) {
    asm volatile(
        "mma.sync.aligned.m16n8k16.row.col.f32.f16.f16.f32 "
        "{%0,%1,%2,%3}, {%4,%5,%6,%7}, {%8,%9}, {%0,%1,%2,%3};"
        : "+f"(c[0]), "+f"(c[1]), "+f"(c[2]), "+f"(c[3])
        : "r"(a[0]), "r"(a[1]), "r"(a[2]), "r"(a[3]), "r"(b[0]), "r"(b[1]));
}

template <int MODE, int NT>
__global__ __launch_bounds__(256, 2)
void hgemm(const __half* __restrict__ A, const __half* __restrict__ Bm,
           void* __restrict__ Cv, int M, int N, int K,
           const float* __restrict__ bias, const void* __restrict__ res) {
    extern __shared__ char smem[];
    uint32_t sb = smem_u32(smem);

    int tid  = threadIdx.x;
    int wid  = tid >> 5, lane = tid & 31;
    int wm   = wid & 3;
    int wn   = wid >> 2;
    int row0 = blockIdx.y * 128;
    int col0 = blockIdx.x * (NT * 16);
    int lg   = lane >> 2;
    int lt   = lane & 3;

    float cacc[2][NT][4];
#pragma unroll
    for (int mt = 0; mt < 2; mt++)
#pragma unroll
        for (int nt = 0; nt < NT; nt++)
#pragma unroll
            for (int q = 0; q < 4; q++) cacc[mt][nt][q] = 0.f;

    int nk = K >> 6;

    auto load_stage = [&](int kt, int buf) {
        uint32_t sA = sb + buf * STG;
        uint32_t sB = sA + 16384;
#pragma unroll
        for (int i = 0; i < 4; i++) {
            int idx = tid + i * 256;
            int m = idx >> 3, c = idx & 7;
            const __half* src = A + (size_t)(row0 + m) * K + (kt << 6) + (c << 3);
            uint32_t dst = sA + m * 128 + ((c ^ (m & 7)) << 4);
            asm volatile("cp.async.cg.shared.global [%0], [%1], 16;"
                         :: "r"(dst), "l"(src) : "memory");
        }
#pragma unroll
        for (int i = 0; i < NT / 2; i++) {
            int idx = tid + i * 256;
            int k = idx / (2 * NT), c = idx % (2 * NT);
            int n = col0 + (c << 3);
            const __half* src = Bm + (size_t)((kt << 6) + k) * N + (n < N ? n : 0);
            uint32_t dst = sB + k * 256 + (((c & 8) | ((c & 7) ^ (k & 7))) << 4);
            int ssz = (n < N) ? 16 : 0;
            asm volatile("cp.async.cg.shared.global [%0], [%1], 16, %2;"
                         :: "r"(dst), "l"(src), "r"(ssz) : "memory");
        }
        asm volatile("cp.async.commit_group;" ::: "memory");
    };

    uint32_t af[2][2][4], bf[2][NT][2];
    auto load_frags = [&](uint32_t sA, uint32_t sB, int ks, int pb) {
#pragma unroll
        for (int mt = 0; mt < 2; mt++) {
            int m = wm * 32 + mt * 16 + (lane & 15);
            int c = ks * 2 + (lane >> 4);
            uint32_t addr = sA + m * 128 + ((c ^ (m & 7)) << 4);
            asm volatile("ldmatrix.sync.aligned.m8n8.x4.shared.b16 {%0,%1,%2,%3}, [%4];"
                         : "=r"(af[pb][mt][0]), "=r"(af[pb][mt][1]),
                           "=r"(af[pb][mt][2]), "=r"(af[pb][mt][3])
                         : "r"(addr));
        }
#pragma unroll
        for (int np = 0; np < NT / 2; np++) {
            int k  = ks * 16 + (lane & 15);
            int cn = wn * NT + np * 2 + (lane >> 4);
            uint32_t addr = sB + k * 256 + (((cn & 8) | ((cn & 7) ^ (k & 7))) << 4);
            asm volatile("ldmatrix.sync.aligned.m8n8.x4.trans.shared.b16 {%0,%1,%2,%3}, [%4];"
                         : "=r"(bf[pb][np * 2][0]), "=r"(bf[pb][np * 2][1]),
                           "=r"(bf[pb][np * 2 + 1][0]), "=r"(bf[pb][np * 2 + 1][1])
                         : "r"(addr));
        }
    };

    load_stage(0, 0);
    if (nk > 1) load_stage(1, 1);

    for (int kt = 0; kt < nk; kt++) {
        int buf = kt % 3;
        if (kt + 1 < nk) {
            asm volatile("cp.async.wait_group 1;" ::: "memory");
        } else {
            asm volatile("cp.async.wait_group 0;" ::: "memory");
        }
        __syncthreads();
        if (kt + 2 < nk) load_stage(kt + 2, (kt + 2) % 3);

        uint32_t sA = sb + buf * STG;
        uint32_t sB = sA + 16384;

        load_frags(sA, sB, 0, 0);
#pragma unroll
        for (int ks = 0; ks < 4; ks++) {
            int cur = ks & 1;
            if (ks < 3) load_frags(sA, sB, ks + 1, cur ^ 1);
#pragma unroll
            for (int mt = 0; mt < 2; mt++)
#pragma unroll
                for (int nt = 0; nt < NT; nt++)
                    hmma(cacc[mt][nt], af[cur][mt], bf[cur][nt]);
        }
    }
    __syncthreads();

    // ---------------- epilogue ----------------
#pragma unroll
    for (int mt = 0; mt < 2; mt++) {
#pragma unroll
        for (int nt = 0; nt < NT; nt++) {
            int r = row0 + wm * 32 + mt * 16 + lg;
            int c = col0 + wn * (NT * 8) + nt * 8 + lt * 2;
            if (c >= N) continue;
#pragma unroll
            for (int half = 0; half < 2; half++) {
                int rr = r + half * 8;
                float v0 = cacc[mt][nt][half * 2 + 0];
                float v1 = cacc[mt][nt][half * 2 + 1];
                if (MODE == 1) {
                    int rb = rr >> 16, rhw = rr & (HW - 1);
                    const float* rp = (const float*)res + (size_t)rb * Cc * HW + rhw;
                    float o0 = v0 + bias[c]     + rp[(size_t)c * HW];
                    float o1 = v1 + bias[c + 1] + rp[(size_t)(c + 1) * HW];
                    *(__half2*)((__half*)Cv + (size_t)rr * N + c) = __floats2half2_rn(o0, o1);
                } else if (MODE == 2) {
                    *(__half2*)((__half*)Cv + (size_t)rr * N + c) =
                        __floats2half2_rn(gelu_exact(v0 + bias[c]),
                                          gelu_exact(v1 + bias[c + 1]));
                } else if (MODE == 3) {
                    int rb = rr >> 16, rhw = rr & (HW - 1);
                    const __half* rp = (const __half*)res + (size_t)rr * Cc;
                    float* op = (float*)Cv + (size_t)rb * Cc * HW + rhw;
                    float2 rf = __half22float2(*(const __half2*)(rp + c));
                    op[(size_t)c * HW]       = rf.x + v0 + bias[c];
                    op[(size_t)(c + 1) * HW] = rf.y + v1 + bias[c + 1];
                } else {  // MODE 4: gelu + reverse-window scatter to Z (fp16)
                    int p  = c / Cc;
                    int cc = c - p * Cc;
                    int bb = rr >> 12;
                    int hq = (rr >> 6) & 63, wq = rr & 63;
                    int h = (hq << 2) + (p >> 2), w = (wq << 2) + (p & 3);
                    int n = (bb << 16) + (h << 8) + w;
                    *(__half2*)((__half*)Cv + (size_t)n * Cc + cc) =
                        __floats2half2_rn(gelu_exact(v0), gelu_exact(v1));
                }
            }
        }
    }
}

// ---------------- launch ----------------
extern "C" void kernel_launch(void* const* d_in, const int* in_sizes, int n_in,
                              void* d_out, int out_size) {
    const float* x       = (const float*)d_in[0];
    const float* norm1_g = (const float*)d_in[1];
    const float* norm1_b = (const float*)d_in[2];
    const float* w_sed   = (const float*)d_in[3];
    const float* proj_w  = (const float*)d_in[4];
    const float* proj_b  = (const float*)d_in[5];
    const float* norm2_g = (const float*)d_in[6];
    const float* norm2_b = (const float*)d_in[7];
    const float* fc1_w   = (const float*)d_in[8];
    const float* fc1_b   = (const float*)d_in[9];
    const float* fc2_w   = (const float*)d_in[10];
    const float* fc2_b   = (const float*)d_in[11];
    float* out = (float*)d_out;

    __half *wf, *Xw, *Z, *X2, *T, *U, *projH, *fc1H, *fc2H;
    cudaGetSymbolAddress((void**)&wf,    g_wf);
    cudaGetSymbolAddress((void**)&Xw,    g_Xw);
    cudaGetSymbolAddress((void**)&Z,     g_Z);
    cudaGetSymbolAddress((void**)&X2,    g_X2);
    cudaGetSymbolAddress((void**)&T,     g_T);
    cudaGetSymbolAddress((void**)&U,     g_U);
    cudaGetSymbolAddress((void**)&projH, g_projH);
    cudaGetSymbolAddress((void**)&fc1H,  g_fc1H);
    cudaGetSymbolAddress((void**)&fc2H,  g_fc2H);

    const int SMEM = 3 * STG;  // 98304
    cudaFuncSetAttribute((hgemm<1, 6>), cudaFuncAttributeMaxDynamicSharedMemorySize, SMEM);
    cudaFuncSetAttribute((hgemm<2, 8>), cudaFuncAttributeMaxDynamicSharedMemorySize, SMEM);
    cudaFuncSetAttribute((hgemm<3, 6>), cudaFuncAttributeMaxDynamicSharedMemorySize, SMEM);
    cudaFuncSetAttribute((hgemm<4, 8>), cudaFuncAttributeMaxDynamicSharedMemorySize, SMEM);
    cudaFuncSetAttribute(ln1_window_kernel, cudaFuncAttributeMaxDynamicSharedMemorySize, LN1_SMEM);

    // 0. merged prep: wf build + all weight fp16 conversions (one launch)
    prep_kernel<<<WF_BLK + CV_BLK, 256>>>(w_sed, wf, proj_w, projH,
                                          fc1_w, fc1H, fc2_w, fc2H);

    // 1. LN1 + window partition via smem transpose (coalesced x reads)
    ln1_window_kernel<<<NPIX / 64, 128, LN1_SMEM>>>(x, norm1_g, norm1_b, Xw);

    // 2. Sedenion GEMM + GELU + reverse-window scatter -> Z (R8 config, NT=8)
    hgemm<4, 8><<<dim3(DWIN / 128, NWIN / 128), 256, SMEM>>>(
        Xw, wf, Z, NWIN, DWIN, DWIN, nullptr, nullptr);

    // 3. proj + bias + residual(x) -> X2 fp16   (131072 x 192 x 192), 96-wide tiles
    hgemm<1, 6><<<dim3(2, NPIX / 128), 256, SMEM>>>(
        Z, projH, X2, NPIX, Cc, Cc, proj_b, x);

    // 4. LN2 -> T (fp16 in/out)
    ln2_kernel<<<(NPIX * 32 + 255) / 256, 256>>>(X2, norm2_g, norm2_b, T);

    // 5. fc1 + bias + GELU -> U fp16   (131072 x 768 x 192)
    hgemm<2, 8><<<dim3(DH / 128, NPIX / 128), 256, SMEM>>>(
        T, fc1H, U, NPIX, DH, Cc, fc1_b, nullptr);

    // 6. fc2 + bias + residual(X2 fp16), transposed store -> out fp32, 96-wide tiles
    hgemm<3, 6><<<dim3(2, NPIX / 128), 256, SMEM>>>(
        U, fc2H, out, NPIX, Cc, DH, fc2_b, X2);
}